// round 11
// baseline (speedup 1.0000x reference)
#include <cuda_runtime.h>
#include <cuda_fp16.h>
#include <math.h>
#include <stdint.h>

// ---------------- problem constants ----------------
#define Bb   2
#define Nn   8192
#define Ee   1024
#define Hh   16
#define Dd   64
#define Cc   128
#define NCk  64
#define Mm   (Bb*Nn)

// ---------------- device scratch ----------------
__device__ float g_q[(size_t)Mm*Ee];
__device__ float g_k[(size_t)Mm*Ee];
__device__ float g_v[(size_t)Mm*Ee];
__device__ float g_o[(size_t)Mm*Ee];
__device__ float g_A [(size_t)Bb*Hh*NCk*Dd*Dd];
__device__ float g_kv[(size_t)Bb*Hh*NCk*Dd*Dd];
__device__ float g_g1[(size_t)Mm*Dd];
__device__ float g_gd[(size_t)Mm*Ee];             // gate pre-sigmoid = g1 @ Wg2
__device__ uint32_t g_xh[(size_t)Mm*Ee/2];        // x half2, [m][k] K-PERMUTED
__device__ uint32_t g_uh[(size_t)Mm*Ee/2];        // LN-gate out half2, K-PERMUTED
__device__ uint32_t g_Wh[4][(size_t)Ee*Ee/2];     // W^T half2: [n][k] K-PERMUTED
__device__ uint32_t g_Wg1h[(size_t)Dd*Ee/2];      // Wg1^T half2: [n=64][k] K-PERMUTED

// K-permutation within each 16-uint32 (32-half) block:
//   new[4j+i] = orig[j+4i]  (j,i in 0..3)
__device__ __forceinline__ int knew(int o) {
    return (o & ~15) + 4 * (o & 3) + ((o & 15) >> 2);
}

__device__ __forceinline__ float head_slope(int h) {
    return exp2f(-0.5f * (float)(h + 1)) * 1.00001f;
}
__device__ __forceinline__ float silu_f(float v) { return v / (1.0f + expf(-v)); }
__device__ __forceinline__ uint32_t s2u(const void* p) {
    return (uint32_t)__cvta_generic_to_shared(p);
}
__device__ __forceinline__ uint32_t packh2(float a, float b) {
    __half2 h = __floats2half2_rn(a, b);
    return *(uint32_t*)&h;
}

#define CP16(dst, src) \
    asm volatile("cp.async.cg.shared.global [%0], [%1], 16;" :: "r"(dst), "l"(src) : "memory")
#define CP_COMMIT() asm volatile("cp.async.commit_group;" ::: "memory")
#define CP_WAIT2()  asm volatile("cp.async.wait_group 2;" ::: "memory")

__device__ __forceinline__ void mma_f16(
    float c[4], uint32_t a0, uint32_t a1, uint32_t a2, uint32_t a3,
    uint32_t b0, uint32_t b1)
{
    asm volatile(
        "mma.sync.aligned.m16n8k16.row.col.f32.f16.f16.f32 "
        "{%0,%1,%2,%3}, {%4,%5,%6,%7}, {%8,%9}, {%0,%1,%2,%3};"
        : "+f"(c[0]), "+f"(c[1]), "+f"(c[2]), "+f"(c[3])
        : "r"(a0), "r"(a1), "r"(a2), "r"(a3), "r"(b0), "r"(b1));
}

__device__ __forceinline__ uint4 lds128(uint32_t addr)
{
    uint4 r;
    asm volatile("ld.shared.v4.b32 {%0,%1,%2,%3}, [%4];"
                 : "=r"(r.x), "=r"(r.y), "=r"(r.z), "=r"(r.w) : "r"(addr));
    return r;
}

// ============================================================
// Conversion kernels (emit K-PERMUTED layouts)
// ============================================================
__global__ __launch_bounds__(256) void conv_x(const float* __restrict__ x)
{
    size_t f = (size_t)(blockIdx.x * 256 + threadIdx.x);
    const size_t n4 = (size_t)Mm * Ee / 4;
    const size_t stride = (size_t)gridDim.x * 256;
    for (; f < n4; f += stride) {
        float4 v = ((const float4*)x)[f];
        int o0 = (int)(f * 2) & 511;
        size_t rowbase = (f * 2) & ~(size_t)511;
        g_xh[rowbase + knew(o0)]     = packh2(v.x, v.y);
        g_xh[rowbase + knew(o0 + 1)] = packh2(v.z, v.w);
    }
}

__global__ __launch_bounds__(256) void conv_wt(
    const float* __restrict__ Wq, const float* __restrict__ Wk,
    const float* __restrict__ Wv, const float* __restrict__ Wo)
{
    __shared__ float t[32][33];
    const float* W = (blockIdx.z == 0) ? Wq : (blockIdx.z == 1) ? Wk :
                     (blockIdx.z == 2) ? Wv : Wo;
    __half* WT = (__half*)g_Wh[blockIdx.z];
    const int tx = threadIdx.x & 31;
    const int ty = threadIdx.x >> 5;
    const int n0 = blockIdx.x * 32;
    const int k0 = blockIdx.y * 32;
#pragma unroll
    for (int j = 0; j < 32; j += 8)
        t[ty + j][tx] = W[(size_t)(k0 + ty + j) * Ee + n0 + tx];
    __syncthreads();
#pragma unroll
    for (int j = 0; j < 32; j += 8) {
        int k = k0 + tx;
        int kk = knew(k >> 1) * 2 + (k & 1);
        WT[(size_t)(n0 + ty + j) * Ee + kk] = __float2half_rn(t[tx][ty + j]);
    }
}

__global__ __launch_bounds__(256) void conv_wg1(const float* __restrict__ Wg1)
{
    __shared__ float t[32][33];
    __half* WT = (__half*)g_Wg1h;
    const int tx = threadIdx.x & 31;
    const int ty = threadIdx.x >> 5;
    const int n0 = blockIdx.x * 32;
    const int k0 = blockIdx.y * 32;
#pragma unroll
    for (int j = 0; j < 32; j += 8)
        t[ty + j][tx] = Wg1[(size_t)(k0 + ty + j) * Dd + n0 + tx];
    __syncthreads();
#pragma unroll
    for (int j = 0; j < 32; j += 8) {
        int k = k0 + tx;
        int kk = knew(k >> 1) * 2 + (k & 1);
        WT[(size_t)(n0 + ty + j) * Ee + kk] = __float2half_rn(t[tx][ty + j]);
    }
}

// ============================================================
// fp16 mma.sync GEMM, 4-stage cp.async pipeline, LDS.128 frags,
// stage loop unrolled x4 (stage offsets compile-time), precomputed
// uint32 smem frag addresses, incremented global pointers.
// ============================================================
#define RU 16
#define STGH 4

template<int NB, int NI>
__device__ __forceinline__ void gemm_core_f16(
    const uint32_t* __restrict__ A, const uint32_t* __restrict__ Bm,
    float* __restrict__ C, int brow, int bcol, int act, int ldc)
{
    extern __shared__ uint32_t smem[];
    const int stageA = 128 * RU;
    const int stageB = NB * RU;
    uint32_t* As0 = smem;
    uint32_t* Bs0 = smem + STGH * stageA;

    const int tid  = threadIdx.x;
    const int wid  = tid >> 5;
    const int lane = tid & 31;
    const int g = lane >> 2, t = lane & 3;
    const int wm = (wid & 3) * 32;
    const int wn = (wid >> 2) * (NI * 8);

    // ---- G2S plan ----
    const int ar0 = tid >> 2, ap0 = (tid & 3) * 4;
    const int ar1 = (tid + 256) >> 2;
    const uint32_t* Ag0 = A + (size_t)(brow + ar0) * 512 + ap0;
    const uint32_t* Ag1 = A + (size_t)(brow + ar1) * 512 + ap0;
    const uint32_t dA0 = s2u(As0 + ar0 * RU + ap0);
    const uint32_t dA1 = s2u(As0 + ar1 * RU + ap0);

    const uint32_t* Bg0 = Bm + (size_t)(bcol + ar0) * 512 + ap0;
    const uint32_t dB0 = s2u(Bs0 + ar0 * RU + ap0);
    const uint32_t* Bg1 = Bm + (size_t)(bcol + ar1) * 512 + ap0;
    const uint32_t dB1 = s2u(Bs0 + ar1 * RU + ap0);

    const uint32_t sAb = stageA * 4;    // stage stride bytes
    const uint32_t sBb = stageB * 4;

    // ---- precomputed frag smem byte addresses (stage 0) ----
    uint32_t aAdr[2][2];
#pragma unroll
    for (int mi = 0; mi < 2; mi++) {
        const int m = wm + mi * 16 + g;
        aAdr[mi][0] = s2u(As0 + m * RU + 4 * t);
        aAdr[mi][1] = s2u(As0 + (m + 8) * RU + 4 * t);
    }
    uint32_t bAdr[NI];
#pragma unroll
    for (int ni = 0; ni < NI; ni++)
        bAdr[ni] = s2u(Bs0 + (wn + ni * 8 + g) * RU + 4 * t);

    float acc[2][NI][4];
#pragma unroll
    for (int mi = 0; mi < 2; mi++)
#pragma unroll
        for (int ni = 0; ni < NI; ni++)
#pragma unroll
            for (int j = 0; j < 4; j++) acc[mi][ni][j] = 0.0f;

    // prologue: stages 0..2
#pragma unroll
    for (int p = 0; p < 3; p++) {
        CP16(dA0 + p * sAb, Ag0 + p * 16);
        CP16(dA1 + p * sAb, Ag1 + p * 16);
        CP16(dB0 + p * sBb, Bg0 + p * 16);
        if (NB == 128) CP16(dB1 + p * sBb, Bg1 + p * 16);
        CP_COMMIT();
    }

    // prefetch source pointers (stage c+3)
    const uint32_t* agp0 = Ag0 + 48;
    const uint32_t* agp1 = Ag1 + 48;
    const uint32_t* bgp0 = Bg0 + 48;
    const uint32_t* bgp1 = Bg1 + 48;

#pragma unroll 1
    for (int cc = 0; cc < 32; cc += 4) {
#pragma unroll
        for (int s = 0; s < 4; s++) {
            const int c = cc + s;
            CP_WAIT2();
            __syncthreads();

            if (c < 29) {
                const uint32_t pofA = ((s + 3) & 3) * sAb;
                const uint32_t pofB = ((s + 3) & 3) * sBb;
                CP16(dA0 + pofA, agp0);
                CP16(dA1 + pofA, agp1);
                CP16(dB0 + pofB, bgp0);
                if (NB == 128) CP16(dB1 + pofB, bgp1);
                CP_COMMIT();
                agp0 += 16; agp1 += 16; bgp0 += 16;
                if (NB == 128) bgp1 += 16;
            }

            const uint32_t offA = s * sAb;     // compile-time per unrolled s
            const uint32_t offB = s * sBb;

            uint4 Af[2][2];
#pragma unroll
            for (int mi = 0; mi < 2; mi++) {
                Af[mi][0] = lds128(aAdr[mi][0] + offA);
                Af[mi][1] = lds128(aAdr[mi][1] + offA);
            }
            uint4 Bf[NI];
#pragma unroll
            for (int ni = 0; ni < NI; ni++)
                Bf[ni] = lds128(bAdr[ni] + offB);

#pragma unroll
            for (int mi = 0; mi < 2; mi++)
#pragma unroll
                for (int ni = 0; ni < NI; ni++)
                    mma_f16(acc[mi][ni],
                            Af[mi][0].x, Af[mi][1].x, Af[mi][0].y, Af[mi][1].y,
                            Bf[ni].x, Bf[ni].y);
#pragma unroll
            for (int mi = 0; mi < 2; mi++)
#pragma unroll
                for (int ni = 0; ni < NI; ni++)
                    mma_f16(acc[mi][ni],
                            Af[mi][0].z, Af[mi][1].z, Af[mi][0].w, Af[mi][1].w,
                            Bf[ni].z, Bf[ni].w);
        }
    }

    // epilogue
#pragma unroll
    for (int mi = 0; mi < 2; mi++) {
        const int r0 = brow + wm + mi * 16 + g;
#pragma unroll
        for (int ni = 0; ni < NI; ni++) {
            const int col = bcol + wn + ni * 8 + 2 * t;
            float v0 = acc[mi][ni][0], v1 = acc[mi][ni][1];
            float v2 = acc[mi][ni][2], v3 = acc[mi][ni][3];
            if (act) { v0 = silu_f(v0); v1 = silu_f(v1); v2 = silu_f(v2); v3 = silu_f(v3); }
            float2 lo; lo.x = v0; lo.y = v1;
            float2 hi; hi.x = v2; hi.y = v3;
            *(float2*)(C + (size_t)r0 * ldc + col) = lo;
            *(float2*)(C + (size_t)(r0 + 8) * ldc + col) = hi;
        }
    }
}

#define GEMM_SMEM_BIG (STGH * (128*RU + 128*RU) * 4)
#define GEMM_SMEM_G1  (STGH * (128*RU + 64*RU) * 4)

__global__ __launch_bounds__(256) void gemm_qkv_f16()
{
    float* C = (blockIdx.z == 0) ? g_q : (blockIdx.z == 1) ? g_k : g_v;
    gemm_core_f16<128, 8>(g_xh, g_Wh[blockIdx.z], C,
                          blockIdx.y * 128, blockIdx.x * 128, 1, Ee);
}

__global__ __launch_bounds__(256) void gemm_out_f16(float* __restrict__ C)
{
    gemm_core_f16<128, 8>(g_uh, g_Wh[3], C,
                          blockIdx.y * 128, blockIdx.x * 128, 0, Ee);
}

__global__ __launch_bounds__(256) void gemm_g1_f16()
{
    gemm_core_f16<64, 4>(g_xh, g_Wg1h, g_g1,
                         blockIdx.x * 128, 0, 0, Dd);
}

// ============================================================
// gd = g1 @ Wg2  (fp32 FFMA). M=16384, N=1024, K=64.
// ============================================================
__global__ __launch_bounds__(256) void sgemm_gd(const float* __restrict__ Wg2)
{
    __shared__ float As[2][8][128];
    __shared__ float Bs[2][8][128];

    const float* A = g_g1;
    const int N = Ee, K = Dd;

    const int tid  = threadIdx.x;
    const int tx   = tid & 15;
    const int ty   = tid >> 4;
    const int brow = blockIdx.y * 128;
    const int bcol = blockIdx.x * 128;

    const int arow = tid >> 1;
    const int acol = (tid & 1) * 4;
    const int bkr  = tid >> 5;
    const int bcl  = (tid & 31) * 4;

    const float* Ap = A + (size_t)(brow + arow) * K + acol;
    const float* Bp = Wg2 + (size_t)bkr * N + bcol + bcl;

    float4 ar = *(const float4*)Ap;
    float4 br = *(const float4*)Bp;
    As[0][acol + 0][arow] = ar.x;
    As[0][acol + 1][arow] = ar.y;
    As[0][acol + 2][arow] = ar.z;
    As[0][acol + 3][arow] = ar.w;
    *(float4*)&Bs[0][bkr][bcl] = br;
    __syncthreads();

    float acc[8][8];
#pragma unroll
    for (int i = 0; i < 8; i++)
#pragma unroll
        for (int j = 0; j < 8; j++) acc[i][j] = 0.0f;

    int buf = 0;
    for (int k0 = 8; k0 <= K; k0 += 8) {
        if (k0 < K) {
            ar = *(const float4*)(Ap + k0);
            br = *(const float4*)(Bp + (size_t)k0 * N);
        }
#pragma unroll
        for (int kk = 0; kk < 8; kk++) {
            float af[8], bf[8];
            *(float4*)&af[0] = *(float4*)&As[buf][kk][ty * 8];
            *(float4*)&af[4] = *(float4*)&As[buf][kk][ty * 8 + 4];
            *(float4*)&bf[0] = *(float4*)&Bs[buf][kk][tx * 8];
            *(float4*)&bf[4] = *(float4*)&Bs[buf][kk][tx * 8 + 4];
#pragma unroll
            for (int i = 0; i < 8; i++)
#pragma unroll
                for (int j = 0; j < 8; j++)
                    acc[i][j] = fmaf(af[i], bf[j], acc[i][j]);
        }
        if (k0 < K) {
            buf ^= 1;
            As[buf][acol + 0][arow] = ar.x;
            As[buf][acol + 1][arow] = ar.y;
            As[buf][acol + 2][arow] = ar.z;
            As[buf][acol + 3][arow] = ar.w;
            *(float4*)&Bs[buf][bkr][bcl] = br;
            __syncthreads();
        }
    }

#pragma unroll
    for (int i = 0; i < 8; i++) {
        float* Cp = g_gd + (size_t)(brow + ty * 8 + i) * N + bcol + tx * 8;
#pragma unroll
        for (int j0 = 0; j0 < 8; j0 += 4) {
            float4 o;
            o.x = acc[i][j0 + 0];
            o.y = acc[i][j0 + 1];
            o.z = acc[i][j0 + 2];
            o.w = acc[i][j0 + 3];
            *(float4*)(Cp + j0) = o;
        }
    }
}

// ============================================================
// Intra-chunk attention + per-chunk kv contribution A_c (fp32)
// ============================================================
#define SM_QT   0
#define SM_KT   (64*132)
#define SM_VS   (2*64*132)
#define SM_SS   (2*64*132 + 128*68)
#define SM_LAM  (2*64*132 + 128*68 + 128*129)
#define SMEM_INTRA_FLOATS (2*64*132 + 128*68 + 128*129 + 128)

__global__ __launch_bounds__(256) void attn_intra(
    const float* __restrict__ q, const float* __restrict__ k,
    const float* __restrict__ v)
{
    extern __shared__ float sm[];
    float* qT  = sm + SM_QT;
    float* kT  = sm + SM_KT;
    float* vs  = sm + SM_VS;
    float* Ss  = sm + SM_SS;
    float* lamk = sm + SM_LAM;

    const int c = blockIdx.x, h = blockIdx.y, b = blockIdx.z;
    const int tid = threadIdx.x;
    const float s = head_slope(h);
    const size_t base = ((size_t)b * Nn + (size_t)c * Cc) * Ee + (size_t)h * Dd;

#pragma unroll
    for (int t = 0; t < 8; t++) {
        int e = tid + t * 256;
        int row = e >> 4;
        int d4 = (e & 15) * 4;
        const size_t g = base + (size_t)row * Ee + d4;
        float4 qv = *(const float4*)(q + g);
        qT[(d4 + 0) * 132 + row] = qv.x;
        qT[(d4 + 1) * 132 + row] = qv.y;
        qT[(d4 + 2) * 132 + row] = qv.z;
        qT[(d4 + 3) * 132 + row] = qv.w;
        float4 kv4 = *(const float4*)(k + g);
        kT[(d4 + 0) * 132 + row] = kv4.x;
        kT[(d4 + 1) * 132 + row] = kv4.y;
        kT[(d4 + 2) * 132 + row] = kv4.z;
        kT[(d4 + 3) * 132 + row] = kv4.w;
        *(float4*)&vs[row * 68 + d4] = *(const float4*)(v + g);
    }
    if (tid < 128) lamk[tid] = expf(-s * (float)(Cc - 1 - tid));
    __syncthreads();

    const int tx = tid & 15, ty = tid >> 4;

    float acc[8][8];
#pragma unroll
    for (int i = 0; i < 8; i++)
#pragma unroll
        for (int j = 0; j < 8; j++) acc[i][j] = 0.0f;

    for (int d = 0; d < 64; d++) {
        float af[8], bf[8];
        *(float4*)&af[0] = *(float4*)&qT[d * 132 + ty * 8];
        *(float4*)&af[4] = *(float4*)&qT[d * 132 + ty * 8 + 4];
        *(float4*)&bf[0] = *(float4*)&kT[d * 132 + tx * 8];
        *(float4*)&bf[4] = *(float4*)&kT[d * 132 + tx * 8 + 4];
#pragma unroll
        for (int i = 0; i < 8; i++)
#pragma unroll
            for (int j = 0; j < 8; j++)
                acc[i][j] = fmaf(af[i], bf[j], acc[i][j]);
    }
#pragma unroll
    for (int ii = 0; ii < 8; ii++) {
        int i = ty * 8 + ii;
#pragma unroll
        for (int jj = 0; jj < 8; jj++) {
            int j = tx * 8 + jj;
            float val = 0.0f;
            if (i >= j) val = acc[ii][jj] * expf(-s * (float)(i - j));
            Ss[i * 129 + j] = val;
        }
    }
    __syncthreads();

    float oc[8][4];
#pragma unroll
    for (int i = 0; i < 8; i++)
#pragma unroll
        for (int j = 0; j < 4; j++) oc[i][j] = 0.0f;

    for (int j = 0; j < 128; j++) {
        float bv[4];
        *(float4*)bv = *(float4*)&vs[j * 68 + tx * 4];
#pragma unroll
        for (int ii = 0; ii < 8; ii++) {
            float a = Ss[(ty * 8 + ii) * 129 + j];
#pragma unroll
            for (int dd = 0; dd < 4; dd++)
                oc[ii][dd] = fmaf(a, bv[dd], oc[ii][dd]);
        }
    }
#pragma unroll
    for (int ii = 0; ii < 8; ii++) {
        float4 o;
        o.x = oc[ii][0]; o.y = oc[ii][1]; o.z = oc[ii][2]; o.w = oc[ii][3];
        *(float4*)(g_o + base + (size_t)(ty * 8 + ii) * Ee + tx * 4) = o;
    }

    float ac[4][4];
#pragma unroll
    for (int i = 0; i < 4; i++)
#pragma unroll
        for (int j = 0; j < 4; j++) ac[i][j] = 0.0f;

    const int dr = ty * 4;
    for (int j = 0; j < 128; j++) {
        float lam = lamk[j];
        float bv[4];
        *(float4*)bv = *(float4*)&vs[j * 68 + tx * 4];
#pragma unroll
        for (int i = 0; i < 4; i++) {
            float a = kT[(dr + i) * 132 + j] * lam;
#pragma unroll
            for (int e2 = 0; e2 < 4; e2++)
                ac[i][e2] = fmaf(a, bv[e2], ac[i][e2]);
        }
    }
    float* Ab = g_A + ((((size_t)b * Hh + h) * NCk + c) * (Dd * Dd));
#pragma unroll
    for (int i = 0; i < 4; i++) {
        float4 o;
        o.x = ac[i][0]; o.y = ac[i][1]; o.z = ac[i][2]; o.w = ac[i][3];
        *(float4*)&Ab[(dr + i) * Dd + tx * 4] = o;
    }
}

// ============================================================
// kv prefix scan: one (b,h,element) chain per thread
// ============================================================
__global__ __launch_bounds__(256) void kv_scan()
{
    const int gidx = blockIdx.x * 256 + threadIdx.x;
    const int bh = gidx >> 12;
    const int e  = gidx & 4095;
    const int h  = bh & 15;
    const float s = head_slope(h);
    const float lamc = expf(-s * (float)Cc);

    size_t off = (size_t)bh * NCk * (Dd * Dd) + e;
    float kv = 0.0f;
#pragma unroll 4
    for (int c = 0; c < NCk; c++) {
        g_kv[off] = kv;
        kv = fmaf(lamc, kv, g_A[off]);
        off += Dd * Dd;
    }
}

// ============================================================
// Inter-chunk: o += lam_q[i] * (q @ kv_prefix)
// ============================================================
#define SMEM_INTER_FLOATS (128*68 + 64*68)

__global__ __launch_bounds__(256) void attn_inter(const float* __restrict__ q)
{
    extern __shared__ float sm[];
    float* qs  = sm;
    float* kvs = sm + 128 * 68;

    const int c = blockIdx.x, h = blockIdx.y, b = blockIdx.z;
    const int tid = threadIdx.x;
    const float s = head_slope(h);
    const size_t base = ((size_t)b * Nn + (size_t)c * Cc) * Ee + (size_t)h * Dd;

#pragma unroll
    for (int t = 0; t < 8; t++) {
        int e = tid + t * 256;
        int row = e >> 4;
        int d4 = (e & 15) * 4;
        *(float4*)&qs[row * 68 + d4] = *(const float4*)(q + base + (size_t)row * Ee + d4);
    }
    const float* kvp = g_kv + (((size_t)b * Hh + h) * NCk + c) * (Dd * Dd);
#pragma unroll
    for (int t = 0; t < 4; t++) {
        int e = tid + t * 256;
        int row = e >> 4;
        int d4 = (e & 15) * 4;
        *(float4*)&kvs[row * 68 + d4] = *(const float4*)(kvp + row * Dd + d4);
    }
    __syncthreads();

    const int tx = tid & 15, ty = tid >> 4;
    float oc[8][4];
#pragma unroll
    for (int i = 0; i < 8; i++)
#pragma unroll
        for (int j = 0; j < 4; j++) oc[i][j] = 0.0f;

    for (int e2 = 0; e2 < 64; e2++) {
        float bv[4];
        *(float4*)bv = *(float4*)&kvs[e2 * 68 + tx * 4];
#pragma unroll
        for (int ii = 0; ii < 8; ii++) {
            float a = qs[(ty * 8 + ii) * 68 + e2];
#pragma unroll
            for (int dd = 0; dd < 4; dd++)
                oc[ii][dd] = fmaf(a, bv[dd], oc[ii][dd]);
        }
    }
#pragma unroll
    for (int ii = 0; ii < 8; ii++) {
        int i = ty * 8 + ii;
        float lamq = expf(-s * (float)(i + 1));
        float* op = g_o + base + (size_t)i * Ee + tx * 4;
        float4 prev = *(float4*)op;
        prev.x = fmaf(lamq, oc[ii][0], prev.x);
        prev.y = fmaf(lamq, oc[ii][1], prev.y);
        prev.z = fmaf(lamq, oc[ii][2], prev.z);
        prev.w = fmaf(lamq, oc[ii][3], prev.w);
        *(float4*)op = prev;
    }
}

// ============================================================
// LayerNorm + sigmoid(gd) * -> g_uh (half, K-PERMUTED)
// ============================================================
__global__ __launch_bounds__(256) void ln_gate(
    const float* __restrict__ gamma, const float* __restrict__ beta)
{
    __shared__ float os[8 * 1024];
    __shared__ float wsum[8], wsq[8];
    __shared__ float mu_s[8], rs_s[8];

    const int tid = threadIdx.x;
    const size_t row0 = (size_t)blockIdx.x * 8;

#pragma unroll
    for (int t = 0; t < 8; t++) {
        int e = tid + t * 256;
        int r = e >> 8;
        int c4 = (e & 255) * 4;
        *(float4*)&os[r * 1024 + c4] = *(const float4*)(g_o + (row0 + r) * 1024 + c4);
    }
    __syncthreads();

    const int lane = tid & 31, wid = tid >> 5;

    for (int r = 0; r < 8; r++) {
        float sum = 0.0f;
#pragma unroll
        for (int t = 0; t < 4; t++) sum += os[r * 1024 + tid + t * 256];
#pragma unroll
        for (int o = 16; o; o >>= 1) sum += __shfl_xor_sync(0xffffffffu, sum, o);
        if (lane == 0) wsum[wid] = sum;
        __syncthreads();
        if (tid == 0) {
            float S = 0.0f;
            for (int w = 0; w < 8; w++) S += wsum[w];
            mu_s[r] = S * (1.0f / 1024.0f);
        }
        __syncthreads();
    }
    for (int r = 0; r < 8; r++) {
        float mu = mu_s[r];
        float sq = 0.0f;
#pragma unroll
        for (int t = 0; t < 4; t++) {
            float d = os[r * 1024 + tid + t * 256] - mu;
            sq = fmaf(d, d, sq);
        }
#pragma unroll
        for (int o = 16; o; o >>= 1) sq += __shfl_xor_sync(0xffffffffu, sq, o);
        if (lane == 0) wsq[wid] = sq;
        __syncthreads();
        if (tid == 0) {
            float Q = 0.0f;
            for (int w = 0; w < 8; w++) Q += wsq[w];
            rs_s[r] = rsqrtf(Q * (1.0f / 1024.0f) + 1e-5f);
        }
        __syncthreads();
    }

    const int r = wid;
    const int cbase = lane * 4;
    const float mu = mu_s[r];
    const float rs = rs_s[r];
#pragma unroll
    for (int t = 0; t < 8; t++) {
        int col = cbase + t * 128;
        float4 ov = *(float4*)&os[r * 1024 + col];
        float4 gd = *(const float4*)(g_gd + (row0 + r) * 1024 + col);
        float4 gm = *(const float4*)(gamma + col);
        float4 bt = *(const float4*)(beta + col);
        float ux = (fmaf((ov.x - mu) * rs, gm.x, bt.x)) * (1.0f / (1.0f + expf(-gd.x)));
        float uy = (fmaf((ov.y - mu) * rs, gm.y, bt.y)) * (1.0f / (1.0f + expf(-gd.y)));
        float uz = (fmaf((ov.z - mu) * rs, gm.z, bt.z)) * (1.0f / (1.0f + expf(-gd.z)));
        float uw = (fmaf((ov.w - mu) * rs, gm.w, bt.w)) * (1.0f / (1.0f + expf(-gd.w)));
        int o0 = col >> 1;
        size_t rb = (row0 + r) * 512;
        g_uh[rb + knew(o0)]     = packh2(ux, uy);
        g_uh[rb + knew(o0 + 1)] = packh2(uz, uw);
    }
}

// ============================================================
// host launch
// ============================================================
extern "C" void kernel_launch(void* const* d_in, const int* in_sizes, int n_in,
                              void* d_out, int out_size)
{
    const float* x     = (const float*)d_in[0];
    const float* Wq    = (const float*)d_in[1];
    const float* Wk    = (const float*)d_in[2];
    const float* Wv    = (const float*)d_in[3];
    const float* Wo    = (const float*)d_in[4];
    const float* gamma = (const float*)d_in[5];
    const float* beta  = (const float*)d_in[6];
    const float* Wg1   = (const float*)d_in[7];
    const float* Wg2   = (const float*)d_in[8];
    float* out = (float*)d_out;

    static bool init_done = false;
    static float *qp, *kp, *vp;
    if (!init_done) {
        cudaGetSymbolAddress((void**)&qp, g_q);
        cudaGetSymbolAddress((void**)&kp, g_k);
        cudaGetSymbolAddress((void**)&vp, g_v);
        cudaFuncSetAttribute(attn_intra, cudaFuncAttributeMaxDynamicSharedMemorySize,
                             SMEM_INTRA_FLOATS * (int)sizeof(float));
        cudaFuncSetAttribute(attn_inter, cudaFuncAttributeMaxDynamicSharedMemorySize,
                             SMEM_INTER_FLOATS * (int)sizeof(float));
        cudaFuncSetAttribute(gemm_qkv_f16, cudaFuncAttributeMaxDynamicSharedMemorySize,
                             GEMM_SMEM_BIG);
        cudaFuncSetAttribute(gemm_out_f16, cudaFuncAttributeMaxDynamicSharedMemorySize,
                             GEMM_SMEM_BIG);
        cudaFuncSetAttribute(gemm_g1_f16, cudaFuncAttributeMaxDynamicSharedMemorySize,
                             GEMM_SMEM_G1);
        init_done = true;
    }

    const int smem_intra = SMEM_INTRA_FLOATS * (int)sizeof(float);
    const int smem_inter = SMEM_INTER_FLOATS * (int)sizeof(float);

    dim3 blk(256);

    conv_x<<<4096, blk>>>(x);
    conv_wt<<<dim3(32, 32, 4), blk>>>(Wq, Wk, Wv, Wo);
    conv_wg1<<<dim3(2, 32), blk>>>(Wg1);

    gemm_qkv_f16<<<dim3(Ee / 128, Mm / 128, 3), blk, GEMM_SMEM_BIG>>>();
    gemm_g1_f16<<<Mm / 128, blk, GEMM_SMEM_G1>>>();
    sgemm_gd<<<dim3(Ee / 128, Mm / 128), blk>>>(Wg2);

    attn_intra<<<dim3(NCk, Hh, Bb), blk, smem_intra>>>(qp, kp, vp);
    kv_scan<<<512, blk>>>();
    attn_inter<<<dim3(NCk, Hh, Bb), blk, smem_inter>>>(qp);

    ln_gate<<<Mm / 8, blk>>>(gamma, beta);

    gemm_out_f16<<<dim3(Ee / 128, Mm / 128), blk, GEMM_SMEM_BIG>>>(out);
}

// round 12
// speedup vs baseline: 1.0174x; 1.0174x over previous
#include <cuda_runtime.h>
#include <cuda_fp16.h>
#include <math.h>
#include <stdint.h>

// ---------------- problem constants ----------------
#define Bb   2
#define Nn   8192
#define Ee   1024
#define Hh   16
#define Dd   64
#define Cc   128
#define NCk  64
#define Mm   (Bb*Nn)

// ---------------- device scratch ----------------
__device__ float g_q[(size_t)Mm*Ee];
__device__ float g_k[(size_t)Mm*Ee];
__device__ float g_v[(size_t)Mm*Ee];
__device__ float g_o[(size_t)Mm*Ee];
__device__ float g_A [(size_t)Bb*Hh*NCk*Dd*Dd];
__device__ float g_kv[(size_t)Bb*Hh*NCk*Dd*Dd];
__device__ float g_g1[(size_t)Mm*Dd];
__device__ float g_gd[(size_t)Mm*Ee];             // gate pre-sigmoid = g1 @ Wg2
__device__ uint32_t g_xh[(size_t)Mm*Ee/2];        // x half2, [m][k] K-PERMUTED
__device__ uint32_t g_uh[(size_t)Mm*Ee/2];        // LN-gate out half2, K-PERMUTED
__device__ uint32_t g_Wh[4][(size_t)Ee*Ee/2];     // W^T half2: [n][k] K-PERMUTED
__device__ uint32_t g_Wg1h[(size_t)Dd*Ee/2];      // Wg1^T half2: [n=64][k] K-PERMUTED

// K-permutation within each 16-uint32 (32-half) block:
//   new[4j+i] = orig[j+4i]  (j,i in 0..3)
__device__ __forceinline__ int knew(int o) {
    return (o & ~15) + 4 * (o & 3) + ((o & 15) >> 2);
}

__device__ __forceinline__ float head_slope(int h) {
    return exp2f(-0.5f * (float)(h + 1)) * 1.00001f;
}
__device__ __forceinline__ float silu_f(float v) { return v / (1.0f + expf(-v)); }
__device__ __forceinline__ uint32_t s2u(const void* p) {
    return (uint32_t)__cvta_generic_to_shared(p);
}
__device__ __forceinline__ uint32_t packh2(float a, float b) {
    __half2 h = __floats2half2_rn(a, b);
    return *(uint32_t*)&h;
}

#define CP16(dst, src) \
    asm volatile("cp.async.cg.shared.global [%0], [%1], 16;" :: "r"(dst), "l"(src) : "memory")
#define CP_COMMIT() asm volatile("cp.async.commit_group;" ::: "memory")
#define CP_WAIT2()  asm volatile("cp.async.wait_group 2;" ::: "memory")

__device__ __forceinline__ void mma_f16(
    float c[4], uint32_t a0, uint32_t a1, uint32_t a2, uint32_t a3,
    uint32_t b0, uint32_t b1)
{
    asm volatile(
        "mma.sync.aligned.m16n8k16.row.col.f32.f16.f16.f32 "
        "{%0,%1,%2,%3}, {%4,%5,%6,%7}, {%8,%9}, {%0,%1,%2,%3};"
        : "+f"(c[0]), "+f"(c[1]), "+f"(c[2]), "+f"(c[3])
        : "r"(a0), "r"(a1), "r"(a2), "r"(a3), "r"(b0), "r"(b1));
}

__device__ __forceinline__ uint4 lds128(uint32_t addr)
{
    uint4 r;
    asm volatile("ld.shared.v4.b32 {%0,%1,%2,%3}, [%4];"
                 : "=r"(r.x), "=r"(r.y), "=r"(r.z), "=r"(r.w) : "r"(addr));
    return r;
}

// ============================================================
// Conversion kernels (emit K-PERMUTED layouts)
// ============================================================
__global__ __launch_bounds__(256) void conv_x(const float* __restrict__ x)
{
    size_t f = (size_t)(blockIdx.x * 256 + threadIdx.x);
    const size_t n4 = (size_t)Mm * Ee / 4;
    const size_t stride = (size_t)gridDim.x * 256;
    for (; f < n4; f += stride) {
        float4 v = ((const float4*)x)[f];
        int o0 = (int)(f * 2) & 511;
        size_t rowbase = (f * 2) & ~(size_t)511;
        g_xh[rowbase + knew(o0)]     = packh2(v.x, v.y);
        g_xh[rowbase + knew(o0 + 1)] = packh2(v.z, v.w);
    }
}

__global__ __launch_bounds__(256) void conv_wt(
    const float* __restrict__ Wq, const float* __restrict__ Wk,
    const float* __restrict__ Wv, const float* __restrict__ Wo)
{
    __shared__ float t[32][33];
    const float* W = (blockIdx.z == 0) ? Wq : (blockIdx.z == 1) ? Wk :
                     (blockIdx.z == 2) ? Wv : Wo;
    __half* WT = (__half*)g_Wh[blockIdx.z];
    const int tx = threadIdx.x & 31;
    const int ty = threadIdx.x >> 5;
    const int n0 = blockIdx.x * 32;
    const int k0 = blockIdx.y * 32;
#pragma unroll
    for (int j = 0; j < 32; j += 8)
        t[ty + j][tx] = W[(size_t)(k0 + ty + j) * Ee + n0 + tx];
    __syncthreads();
#pragma unroll
    for (int j = 0; j < 32; j += 8) {
        int k = k0 + tx;
        int kk = knew(k >> 1) * 2 + (k & 1);
        WT[(size_t)(n0 + ty + j) * Ee + kk] = __float2half_rn(t[tx][ty + j]);
    }
}

__global__ __launch_bounds__(256) void conv_wg1(const float* __restrict__ Wg1)
{
    __shared__ float t[32][33];
    __half* WT = (__half*)g_Wg1h;
    const int tx = threadIdx.x & 31;
    const int ty = threadIdx.x >> 5;
    const int n0 = blockIdx.x * 32;
    const int k0 = blockIdx.y * 32;
#pragma unroll
    for (int j = 0; j < 32; j += 8)
        t[ty + j][tx] = Wg1[(size_t)(k0 + ty + j) * Dd + n0 + tx];
    __syncthreads();
#pragma unroll
    for (int j = 0; j < 32; j += 8) {
        int k = k0 + tx;
        int kk = knew(k >> 1) * 2 + (k & 1);
        WT[(size_t)(n0 + ty + j) * Ee + kk] = __float2half_rn(t[tx][ty + j]);
    }
}

// ============================================================
// fp16 mma.sync GEMM, 128 threads / 4 warps (2m x 2n),
// warp tile 64 x (NB/2): per warp-stage 16 LDS.128 : 8*NB/16 HMMA.
// 4-stage cp.async pipeline, K-permuted LDS.128 fragments.
// ============================================================
#define RU 16
#define STGH 4

template<int NB>
__device__ __forceinline__ void gemm_core_f16(
    const uint32_t* __restrict__ A, const uint32_t* __restrict__ Bm,
    float* __restrict__ C, int brow, int bcol, int act, int ldc)
{
    constexpr int NI = NB / 16;          // b-frags per warp (warp n-tile = NB/2)
    extern __shared__ uint32_t smem[];
    const int stageA = 128 * RU;
    const int stageB = NB * RU;
    uint32_t* As0 = smem;
    uint32_t* Bs0 = smem + STGH * stageA;

    const int tid  = threadIdx.x;        // 0..127
    const int wid  = tid >> 5;           // 0..3
    const int lane = tid & 31;
    const int g = lane >> 2, t = lane & 3;
    const int wm = (wid & 1) * 64;
    const int wn = (wid >> 1) * (NB / 2);

    // ---- G2S plan: r0 = tid>>2 (0..31), 4 row-blocks of 32 ----
    const int r0 = tid >> 2, p0 = (tid & 3) * 4;
    const uint32_t* Ag = A + (size_t)(brow + r0) * 512 + p0;
    const uint32_t* Bg = Bm + (size_t)(bcol + r0) * 512 + p0;
    const uint32_t dA = s2u(As0 + r0 * RU + p0);
    const uint32_t dB = s2u(Bs0 + r0 * RU + p0);

    const uint32_t sAb = stageA * 4;     // stage stride bytes
    const uint32_t sBb = stageB * 4;

    // ---- precomputed frag smem byte addresses (stage 0) ----
    uint32_t aAdr[4];
#pragma unroll
    for (int mi = 0; mi < 4; mi++)
        aAdr[mi] = s2u(As0 + (wm + mi * 16 + g) * RU + 4 * t);
    uint32_t bAdr[NI];
#pragma unroll
    for (int ni = 0; ni < NI; ni++)
        bAdr[ni] = s2u(Bs0 + (wn + ni * 8 + g) * RU + 4 * t);

    float acc[4][NI][4];
#pragma unroll
    for (int mi = 0; mi < 4; mi++)
#pragma unroll
        for (int ni = 0; ni < NI; ni++)
#pragma unroll
            for (int j = 0; j < 4; j++) acc[mi][ni][j] = 0.0f;

    // prologue: stages 0..2
#pragma unroll
    for (int p = 0; p < 3; p++) {
#pragma unroll
        for (int i = 0; i < 4; i++)
            CP16(dA + p * sAb + i * 2048, Ag + p * 16 + (size_t)i * (32 * 512));
#pragma unroll
        for (int i = 0; i < NB / 32; i++)
            CP16(dB + p * sBb + i * 2048, Bg + p * 16 + (size_t)i * (32 * 512));
        CP_COMMIT();
    }

    const uint32_t* agp = Ag + 48;       // stage c+3 source
    const uint32_t* bgp = Bg + 48;

#pragma unroll 1
    for (int cc = 0; cc < 32; cc += 4) {
#pragma unroll
        for (int s = 0; s < 4; s++) {
            const int c = cc + s;
            CP_WAIT2();
            __syncthreads();

            if (c < 29) {
                const uint32_t pofA = ((s + 3) & 3) * sAb;
                const uint32_t pofB = ((s + 3) & 3) * sBb;
#pragma unroll
                for (int i = 0; i < 4; i++)
                    CP16(dA + pofA + i * 2048, agp + (size_t)i * (32 * 512));
#pragma unroll
                for (int i = 0; i < NB / 32; i++)
                    CP16(dB + pofB + i * 2048, bgp + (size_t)i * (32 * 512));
                CP_COMMIT();
                agp += 16; bgp += 16;
            }

            const uint32_t offA = s * sAb;   // compile-time per unrolled s
            const uint32_t offB = s * sBb;

            uint4 Af[4][2];
#pragma unroll
            for (int mi = 0; mi < 4; mi++) {
                Af[mi][0] = lds128(aAdr[mi] + offA);
                Af[mi][1] = lds128(aAdr[mi] + offA + 512);   // row +8 (8*16*4B)
            }
            uint4 Bf[NI];
#pragma unroll
            for (int ni = 0; ni < NI; ni++)
                Bf[ni] = lds128(bAdr[ni] + offB);

#pragma unroll
            for (int mi = 0; mi < 4; mi++)
#pragma unroll
                for (int ni = 0; ni < NI; ni++)
                    mma_f16(acc[mi][ni],
                            Af[mi][0].x, Af[mi][1].x, Af[mi][0].y, Af[mi][1].y,
                            Bf[ni].x, Bf[ni].y);
#pragma unroll
            for (int mi = 0; mi < 4; mi++)
#pragma unroll
                for (int ni = 0; ni < NI; ni++)
                    mma_f16(acc[mi][ni],
                            Af[mi][0].z, Af[mi][1].z, Af[mi][0].w, Af[mi][1].w,
                            Bf[ni].z, Bf[ni].w);
        }
    }

    // epilogue
#pragma unroll
    for (int mi = 0; mi < 4; mi++) {
        const int r = brow + wm + mi * 16 + g;
#pragma unroll
        for (int ni = 0; ni < NI; ni++) {
            const int col = bcol + wn + ni * 8 + 2 * t;
            float v0 = acc[mi][ni][0], v1 = acc[mi][ni][1];
            float v2 = acc[mi][ni][2], v3 = acc[mi][ni][3];
            if (act) { v0 = silu_f(v0); v1 = silu_f(v1); v2 = silu_f(v2); v3 = silu_f(v3); }
            float2 lo; lo.x = v0; lo.y = v1;
            float2 hi; hi.x = v2; hi.y = v3;
            *(float2*)(C + (size_t)r * ldc + col) = lo;
            *(float2*)(C + (size_t)(r + 8) * ldc + col) = hi;
        }
    }
}

#define GEMM_SMEM_BIG (STGH * (128*RU + 128*RU) * 4)
#define GEMM_SMEM_G1  (STGH * (128*RU + 64*RU) * 4)

__global__ __launch_bounds__(128) void gemm_qkv_f16()
{
    float* C = (blockIdx.z == 0) ? g_q : (blockIdx.z == 1) ? g_k : g_v;
    gemm_core_f16<128>(g_xh, g_Wh[blockIdx.z], C,
                       blockIdx.y * 128, blockIdx.x * 128, 1, Ee);
}

__global__ __launch_bounds__(128) void gemm_out_f16(float* __restrict__ C)
{
    gemm_core_f16<128>(g_uh, g_Wh[3], C,
                       blockIdx.y * 128, blockIdx.x * 128, 0, Ee);
}

__global__ __launch_bounds__(128) void gemm_g1_f16()
{
    gemm_core_f16<64>(g_xh, g_Wg1h, g_g1,
                      blockIdx.x * 128, 0, 0, Dd);
}

// ============================================================
// gd = g1 @ Wg2  (fp32 FFMA). M=16384, N=1024, K=64.
// ============================================================
__global__ __launch_bounds__(256) void sgemm_gd(const float* __restrict__ Wg2)
{
    __shared__ float As[2][8][128];
    __shared__ float Bs[2][8][128];

    const float* A = g_g1;
    const int N = Ee, K = Dd;

    const int tid  = threadIdx.x;
    const int tx   = tid & 15;
    const int ty   = tid >> 4;
    const int brow = blockIdx.y * 128;
    const int bcol = blockIdx.x * 128;

    const int arow = tid >> 1;
    const int acol = (tid & 1) * 4;
    const int bkr  = tid >> 5;
    const int bcl  = (tid & 31) * 4;

    const float* Ap = A + (size_t)(brow + arow) * K + acol;
    const float* Bp = Wg2 + (size_t)bkr * N + bcol + bcl;

    float4 ar = *(const float4*)Ap;
    float4 br = *(const float4*)Bp;
    As[0][acol + 0][arow] = ar.x;
    As[0][acol + 1][arow] = ar.y;
    As[0][acol + 2][arow] = ar.z;
    As[0][acol + 3][arow] = ar.w;
    *(float4*)&Bs[0][bkr][bcl] = br;
    __syncthreads();

    float acc[8][8];
#pragma unroll
    for (int i = 0; i < 8; i++)
#pragma unroll
        for (int j = 0; j < 8; j++) acc[i][j] = 0.0f;

    int buf = 0;
    for (int k0 = 8; k0 <= K; k0 += 8) {
        if (k0 < K) {
            ar = *(const float4*)(Ap + k0);
            br = *(const float4*)(Bp + (size_t)k0 * N);
        }
#pragma unroll
        for (int kk = 0; kk < 8; kk++) {
            float af[8], bf[8];
            *(float4*)&af[0] = *(float4*)&As[buf][kk][ty * 8];
            *(float4*)&af[4] = *(float4*)&As[buf][kk][ty * 8 + 4];
            *(float4*)&bf[0] = *(float4*)&Bs[buf][kk][tx * 8];
            *(float4*)&bf[4] = *(float4*)&Bs[buf][kk][tx * 8 + 4];
#pragma unroll
            for (int i = 0; i < 8; i++)
#pragma unroll
                for (int j = 0; j < 8; j++)
                    acc[i][j] = fmaf(af[i], bf[j], acc[i][j]);
        }
        if (k0 < K) {
            buf ^= 1;
            As[buf][acol + 0][arow] = ar.x;
            As[buf][acol + 1][arow] = ar.y;
            As[buf][acol + 2][arow] = ar.z;
            As[buf][acol + 3][arow] = ar.w;
            *(float4*)&Bs[buf][bkr][bcl] = br;
            __syncthreads();
        }
    }

#pragma unroll
    for (int i = 0; i < 8; i++) {
        float* Cp = g_gd + (size_t)(brow + ty * 8 + i) * N + bcol + tx * 8;
#pragma unroll
        for (int j0 = 0; j0 < 8; j0 += 4) {
            float4 o;
            o.x = acc[i][j0 + 0];
            o.y = acc[i][j0 + 1];
            o.z = acc[i][j0 + 2];
            o.w = acc[i][j0 + 3];
            *(float4*)(Cp + j0) = o;
        }
    }
}

// ============================================================
// Intra-chunk attention + per-chunk kv contribution A_c (fp32)
// ============================================================
#define SM_QT   0
#define SM_KT   (64*132)
#define SM_VS   (2*64*132)
#define SM_SS   (2*64*132 + 128*68)
#define SM_LAM  (2*64*132 + 128*68 + 128*129)
#define SMEM_INTRA_FLOATS (2*64*132 + 128*68 + 128*129 + 128)

__global__ __launch_bounds__(256) void attn_intra(
    const float* __restrict__ q, const float* __restrict__ k,
    const float* __restrict__ v)
{
    extern __shared__ float sm[];
    float* qT  = sm + SM_QT;
    float* kT  = sm + SM_KT;
    float* vs  = sm + SM_VS;
    float* Ss  = sm + SM_SS;
    float* lamk = sm + SM_LAM;

    const int c = blockIdx.x, h = blockIdx.y, b = blockIdx.z;
    const int tid = threadIdx.x;
    const float s = head_slope(h);
    const size_t base = ((size_t)b * Nn + (size_t)c * Cc) * Ee + (size_t)h * Dd;

#pragma unroll
    for (int t = 0; t < 8; t++) {
        int e = tid + t * 256;
        int row = e >> 4;
        int d4 = (e & 15) * 4;
        const size_t g = base + (size_t)row * Ee + d4;
        float4 qv = *(const float4*)(q + g);
        qT[(d4 + 0) * 132 + row] = qv.x;
        qT[(d4 + 1) * 132 + row] = qv.y;
        qT[(d4 + 2) * 132 + row] = qv.z;
        qT[(d4 + 3) * 132 + row] = qv.w;
        float4 kv4 = *(const float4*)(k + g);
        kT[(d4 + 0) * 132 + row] = kv4.x;
        kT[(d4 + 1) * 132 + row] = kv4.y;
        kT[(d4 + 2) * 132 + row] = kv4.z;
        kT[(d4 + 3) * 132 + row] = kv4.w;
        *(float4*)&vs[row * 68 + d4] = *(const float4*)(v + g);
    }
    if (tid < 128) lamk[tid] = expf(-s * (float)(Cc - 1 - tid));
    __syncthreads();

    const int tx = tid & 15, ty = tid >> 4;

    float acc[8][8];
#pragma unroll
    for (int i = 0; i < 8; i++)
#pragma unroll
        for (int j = 0; j < 8; j++) acc[i][j] = 0.0f;

    for (int d = 0; d < 64; d++) {
        float af[8], bf[8];
        *(float4*)&af[0] = *(float4*)&qT[d * 132 + ty * 8];
        *(float4*)&af[4] = *(float4*)&qT[d * 132 + ty * 8 + 4];
        *(float4*)&bf[0] = *(float4*)&kT[d * 132 + tx * 8];
        *(float4*)&bf[4] = *(float4*)&kT[d * 132 + tx * 8 + 4];
#pragma unroll
        for (int i = 0; i < 8; i++)
#pragma unroll
            for (int j = 0; j < 8; j++)
                acc[i][j] = fmaf(af[i], bf[j], acc[i][j]);
    }
#pragma unroll
    for (int ii = 0; ii < 8; ii++) {
        int i = ty * 8 + ii;
#pragma unroll
        for (int jj = 0; jj < 8; jj++) {
            int j = tx * 8 + jj;
            float val = 0.0f;
            if (i >= j) val = acc[ii][jj] * expf(-s * (float)(i - j));
            Ss[i * 129 + j] = val;
        }
    }
    __syncthreads();

    float oc[8][4];
#pragma unroll
    for (int i = 0; i < 8; i++)
#pragma unroll
        for (int j = 0; j < 4; j++) oc[i][j] = 0.0f;

    for (int j = 0; j < 128; j++) {
        float bv[4];
        *(float4*)bv = *(float4*)&vs[j * 68 + tx * 4];
#pragma unroll
        for (int ii = 0; ii < 8; ii++) {
            float a = Ss[(ty * 8 + ii) * 129 + j];
#pragma unroll
            for (int dd = 0; dd < 4; dd++)
                oc[ii][dd] = fmaf(a, bv[dd], oc[ii][dd]);
        }
    }
#pragma unroll
    for (int ii = 0; ii < 8; ii++) {
        float4 o;
        o.x = oc[ii][0]; o.y = oc[ii][1]; o.z = oc[ii][2]; o.w = oc[ii][3];
        *(float4*)(g_o + base + (size_t)(ty * 8 + ii) * Ee + tx * 4) = o;
    }

    float ac[4][4];
#pragma unroll
    for (int i = 0; i < 4; i++)
#pragma unroll
        for (int j = 0; j < 4; j++) ac[i][j] = 0.0f;

    const int dr = ty * 4;
    for (int j = 0; j < 128; j++) {
        float lam = lamk[j];
        float bv[4];
        *(float4*)bv = *(float4*)&vs[j * 68 + tx * 4];
#pragma unroll
        for (int i = 0; i < 4; i++) {
            float a = kT[(dr + i) * 132 + j] * lam;
#pragma unroll
            for (int e2 = 0; e2 < 4; e2++)
                ac[i][e2] = fmaf(a, bv[e2], ac[i][e2]);
        }
    }
    float* Ab = g_A + ((((size_t)b * Hh + h) * NCk + c) * (Dd * Dd));
#pragma unroll
    for (int i = 0; i < 4; i++) {
        float4 o;
        o.x = ac[i][0]; o.y = ac[i][1]; o.z = ac[i][2]; o.w = ac[i][3];
        *(float4*)&Ab[(dr + i) * Dd + tx * 4] = o;
    }
}

// ============================================================
// kv prefix scan: one (b,h,element) chain per thread
// ============================================================
__global__ __launch_bounds__(256) void kv_scan()
{
    const int gidx = blockIdx.x * 256 + threadIdx.x;
    const int bh = gidx >> 12;
    const int e  = gidx & 4095;
    const int h  = bh & 15;
    const float s = head_slope(h);
    const float lamc = expf(-s * (float)Cc);

    size_t off = (size_t)bh * NCk * (Dd * Dd) + e;
    float kv = 0.0f;
#pragma unroll 4
    for (int c = 0; c < NCk; c++) {
        g_kv[off] = kv;
        kv = fmaf(lamc, kv, g_A[off]);
        off += Dd * Dd;
    }
}

// ============================================================
// Inter-chunk: o += lam_q[i] * (q @ kv_prefix)
// ============================================================
#define SMEM_INTER_FLOATS (128*68 + 64*68)

__global__ __launch_bounds__(256) void attn_inter(const float* __restrict__ q)
{
    extern __shared__ float sm[];
    float* qs  = sm;
    float* kvs = sm + 128 * 68;

    const int c = blockIdx.x, h = blockIdx.y, b = blockIdx.z;
    const int tid = threadIdx.x;
    const float s = head_slope(h);
    const size_t base = ((size_t)b * Nn + (size_t)c * Cc) * Ee + (size_t)h * Dd;

#pragma unroll
    for (int t = 0; t < 8; t++) {
        int e = tid + t * 256;
        int row = e >> 4;
        int d4 = (e & 15) * 4;
        *(float4*)&qs[row * 68 + d4] = *(const float4*)(q + base + (size_t)row * Ee + d4);
    }
    const float* kvp = g_kv + (((size_t)b * Hh + h) * NCk + c) * (Dd * Dd);
#pragma unroll
    for (int t = 0; t < 4; t++) {
        int e = tid + t * 256;
        int row = e >> 4;
        int d4 = (e & 15) * 4;
        *(float4*)&kvs[row * 68 + d4] = *(const float4*)(kvp + row * Dd + d4);
    }
    __syncthreads();

    const int tx = tid & 15, ty = tid >> 4;
    float oc[8][4];
#pragma unroll
    for (int i = 0; i < 8; i++)
#pragma unroll
        for (int j = 0; j < 4; j++) oc[i][j] = 0.0f;

    for (int e2 = 0; e2 < 64; e2++) {
        float bv[4];
        *(float4*)bv = *(float4*)&kvs[e2 * 68 + tx * 4];
#pragma unroll
        for (int ii = 0; ii < 8; ii++) {
            float a = qs[(ty * 8 + ii) * 68 + e2];
#pragma unroll
            for (int dd = 0; dd < 4; dd++)
                oc[ii][dd] = fmaf(a, bv[dd], oc[ii][dd]);
        }
    }
#pragma unroll
    for (int ii = 0; ii < 8; ii++) {
        int i = ty * 8 + ii;
        float lamq = expf(-s * (float)(i + 1));
        float* op = g_o + base + (size_t)i * Ee + tx * 4;
        float4 prev = *(float4*)op;
        prev.x = fmaf(lamq, oc[ii][0], prev.x);
        prev.y = fmaf(lamq, oc[ii][1], prev.y);
        prev.z = fmaf(lamq, oc[ii][2], prev.z);
        prev.w = fmaf(lamq, oc[ii][3], prev.w);
        *(float4*)op = prev;
    }
}

// ============================================================
// LayerNorm + sigmoid(gd) * -> g_uh (half, K-PERMUTED)
// ============================================================
__global__ __launch_bounds__(256) void ln_gate(
    const float* __restrict__ gamma, const float* __restrict__ beta)
{
    __shared__ float os[8 * 1024];
    __shared__ float wsum[8], wsq[8];
    __shared__ float mu_s[8], rs_s[8];

    const int tid = threadIdx.x;
    const size_t row0 = (size_t)blockIdx.x * 8;

#pragma unroll
    for (int t = 0; t < 8; t++) {
        int e = tid + t * 256;
        int r = e >> 8;
        int c4 = (e & 255) * 4;
        *(float4*)&os[r * 1024 + c4] = *(const float4*)(g_o + (row0 + r) * 1024 + c4);
    }
    __syncthreads();

    const int lane = tid & 31, wid = tid >> 5;

    for (int r = 0; r < 8; r++) {
        float sum = 0.0f;
#pragma unroll
        for (int t = 0; t < 4; t++) sum += os[r * 1024 + tid + t * 256];
#pragma unroll
        for (int o = 16; o; o >>= 1) sum += __shfl_xor_sync(0xffffffffu, sum, o);
        if (lane == 0) wsum[wid] = sum;
        __syncthreads();
        if (tid == 0) {
            float S = 0.0f;
            for (int w = 0; w < 8; w++) S += wsum[w];
            mu_s[r] = S * (1.0f / 1024.0f);
        }
        __syncthreads();
    }
    for (int r = 0; r < 8; r++) {
        float mu = mu_s[r];
        float sq = 0.0f;
#pragma unroll
        for (int t = 0; t < 4; t++) {
            float d = os[r * 1024 + tid + t * 256] - mu;
            sq = fmaf(d, d, sq);
        }
#pragma unroll
        for (int o = 16; o; o >>= 1) sq += __shfl_xor_sync(0xffffffffu, sq, o);
        if (lane == 0) wsq[wid] = sq;
        __syncthreads();
        if (tid == 0) {
            float Q = 0.0f;
            for (int w = 0; w < 8; w++) Q += wsq[w];
            rs_s[r] = rsqrtf(Q * (1.0f / 1024.0f) + 1e-5f);
        }
        __syncthreads();
    }

    const int r = wid;
    const int cbase = lane * 4;
    const float mu = mu_s[r];
    const float rs = rs_s[r];
#pragma unroll
    for (int t = 0; t < 8; t++) {
        int col = cbase + t * 128;
        float4 ov = *(float4*)&os[r * 1024 + col];
        float4 gd = *(const float4*)(g_gd + (row0 + r) * 1024 + col);
        float4 gm = *(const float4*)(gamma + col);
        float4 bt = *(const float4*)(beta + col);
        float ux = (fmaf((ov.x - mu) * rs, gm.x, bt.x)) * (1.0f / (1.0f + expf(-gd.x)));
        float uy = (fmaf((ov.y - mu) * rs, gm.y, bt.y)) * (1.0f / (1.0f + expf(-gd.y)));
        float uz = (fmaf((ov.z - mu) * rs, gm.z, bt.z)) * (1.0f / (1.0f + expf(-gd.z)));
        float uw = (fmaf((ov.w - mu) * rs, gm.w, bt.w)) * (1.0f / (1.0f + expf(-gd.w)));
        int o0 = col >> 1;
        size_t rb = (row0 + r) * 512;
        g_uh[rb + knew(o0)]     = packh2(ux, uy);
        g_uh[rb + knew(o0 + 1)] = packh2(uz, uw);
    }
}

// ============================================================
// host launch
// ============================================================
extern "C" void kernel_launch(void* const* d_in, const int* in_sizes, int n_in,
                              void* d_out, int out_size)
{
    const float* x     = (const float*)d_in[0];
    const float* Wq    = (const float*)d_in[1];
    const float* Wk    = (const float*)d_in[2];
    const float* Wv    = (const float*)d_in[3];
    const float* Wo    = (const float*)d_in[4];
    const float* gamma = (const float*)d_in[5];
    const float* beta  = (const float*)d_in[6];
    const float* Wg1   = (const float*)d_in[7];
    const float* Wg2   = (const float*)d_in[8];
    float* out = (float*)d_out;

    static bool init_done = false;
    static float *qp, *kp, *vp;
    if (!init_done) {
        cudaGetSymbolAddress((void**)&qp, g_q);
        cudaGetSymbolAddress((void**)&kp, g_k);
        cudaGetSymbolAddress((void**)&vp, g_v);
        cudaFuncSetAttribute(attn_intra, cudaFuncAttributeMaxDynamicSharedMemorySize,
                             SMEM_INTRA_FLOATS * (int)sizeof(float));
        cudaFuncSetAttribute(attn_inter, cudaFuncAttributeMaxDynamicSharedMemorySize,
                             SMEM_INTER_FLOATS * (int)sizeof(float));
        cudaFuncSetAttribute(gemm_qkv_f16, cudaFuncAttributeMaxDynamicSharedMemorySize,
                             GEMM_SMEM_BIG);
        cudaFuncSetAttribute(gemm_out_f16, cudaFuncAttributeMaxDynamicSharedMemorySize,
                             GEMM_SMEM_BIG);
        cudaFuncSetAttribute(gemm_g1_f16, cudaFuncAttributeMaxDynamicSharedMemorySize,
                             GEMM_SMEM_G1);
        init_done = true;
    }

    const int smem_intra = SMEM_INTRA_FLOATS * (int)sizeof(float);
    const int smem_inter = SMEM_INTER_FLOATS * (int)sizeof(float);

    dim3 blk(256);
    dim3 blk128(128);

    conv_x<<<4096, blk>>>(x);
    conv_wt<<<dim3(32, 32, 4), blk>>>(Wq, Wk, Wv, Wo);
    conv_wg1<<<dim3(2, 32), blk>>>(Wg1);

    gemm_qkv_f16<<<dim3(Ee / 128, Mm / 128, 3), blk128, GEMM_SMEM_BIG>>>();
    gemm_g1_f16<<<Mm / 128, blk128, GEMM_SMEM_G1>>>();
    sgemm_gd<<<dim3(Ee / 128, Mm / 128), blk>>>(Wg2);

    attn_intra<<<dim3(NCk, Hh, Bb), blk, smem_intra>>>(qp, kp, vp);
    kv_scan<<<512, blk>>>();
    attn_inter<<<dim3(NCk, Hh, Bb), blk, smem_inter>>>(qp);

    ln_gate<<<Mm / 8, blk>>>(gamma, beta);

    gemm_out_f16<<<dim3(Ee / 128, Mm / 128), blk128, GEMM_SMEM_BIG>>>(out);
}

// round 15
// speedup vs baseline: 1.0321x; 1.0144x over previous
#include <cuda_runtime.h>
#include <cuda_fp16.h>
#include <math.h>
#include <stdint.h>

// ---------------- problem constants ----------------
#define Bb   2
#define Nn   8192
#define Ee   1024
#define Hh   16
#define Dd   64
#define Cc   128
#define NCk  64
#define Mm   (Bb*Nn)

// ---------------- device scratch ----------------
__device__ float g_q[(size_t)Mm*Ee];
__device__ float g_k[(size_t)Mm*Ee];
__device__ float g_v[(size_t)Mm*Ee];
__device__ float g_o[(size_t)Mm*Ee];
__device__ float g_A [(size_t)Bb*Hh*NCk*Dd*Dd];
__device__ float g_kv[(size_t)Bb*Hh*NCk*Dd*Dd];
__device__ float g_g1[(size_t)Mm*Dd];
__device__ float g_gd[(size_t)Mm*Ee];             // gate pre-sigmoid = g1 @ Wg2
__device__ uint32_t g_xh[(size_t)Mm*Ee/2];        // x half2, [m][k] K-PERMUTED
__device__ uint32_t g_uh[(size_t)Mm*Ee/2];        // LN-gate out half2, K-PERMUTED
__device__ uint32_t g_Wh[4][(size_t)Ee*Ee/2];     // W^T half2: [n][k] K-PERMUTED
__device__ uint32_t g_Wg1h[(size_t)Dd*Ee/2];      // Wg1^T half2: [n=64][k] K-PERMUTED

// K-permutation within each 16-uint32 (32-half) block:
//   new[4j+i] = orig[j+4i]  (j,i in 0..3)
__device__ __forceinline__ int knew(int o) {
    return (o & ~15) + 4 * (o & 3) + ((o & 15) >> 2);
}

__device__ __forceinline__ float head_slope(int h) {
    return exp2f(-0.5f * (float)(h + 1)) * 1.00001f;
}
__device__ __forceinline__ float silu_f(float v) { return v / (1.0f + expf(-v)); }
__device__ __forceinline__ uint32_t s2u(const void* p) {
    return (uint32_t)__cvta_generic_to_shared(p);
}
__device__ __forceinline__ uint32_t packh2(float a, float b) {
    __half2 h = __floats2half2_rn(a, b);
    return *(uint32_t*)&h;
}

#define CP16(dst, src) \
    asm volatile("cp.async.cg.shared.global [%0], [%1], 16;" :: "r"(dst), "l"(src) : "memory")
#define CP_COMMIT() asm volatile("cp.async.commit_group;" ::: "memory")
#define CP_WAIT2()  asm volatile("cp.async.wait_group 2;" ::: "memory")

__device__ __forceinline__ void mma_f16(
    float c[4], uint32_t a0, uint32_t a1, uint32_t a2, uint32_t a3,
    uint32_t b0, uint32_t b1)
{
    asm volatile(
        "mma.sync.aligned.m16n8k16.row.col.f32.f16.f16.f32 "
        "{%0,%1,%2,%3}, {%4,%5,%6,%7}, {%8,%9}, {%0,%1,%2,%3};"
        : "+f"(c[0]), "+f"(c[1]), "+f"(c[2]), "+f"(c[3])
        : "r"(a0), "r"(a1), "r"(a2), "r"(a3), "r"(b0), "r"(b1));
}

__device__ __forceinline__ uint4 lds128(uint32_t addr)
{
    uint4 r;
    asm volatile("ld.shared.v4.b32 {%0,%1,%2,%3}, [%4];"
                 : "=r"(r.x), "=r"(r.y), "=r"(r.z), "=r"(r.w) : "r"(addr));
    return r;
}

// ============================================================
// Conversion kernels (emit K-PERMUTED layouts)
// ============================================================
__global__ __launch_bounds__(256) void conv_x(const float* __restrict__ x)
{
    size_t f = (size_t)(blockIdx.x * 256 + threadIdx.x);
    const size_t n4 = (size_t)Mm * Ee / 4;
    const size_t stride = (size_t)gridDim.x * 256;
    for (; f < n4; f += stride) {
        float4 v = ((const float4*)x)[f];
        int o0 = (int)(f * 2) & 511;
        size_t rowbase = (f * 2) & ~(size_t)511;
        g_xh[rowbase + knew(o0)]     = packh2(v.x, v.y);
        g_xh[rowbase + knew(o0 + 1)] = packh2(v.z, v.w);
    }
}

__global__ __launch_bounds__(256) void conv_wt(
    const float* __restrict__ Wq, const float* __restrict__ Wk,
    const float* __restrict__ Wv, const float* __restrict__ Wo)
{
    __shared__ float t[32][33];
    const float* W = (blockIdx.z == 0) ? Wq : (blockIdx.z == 1) ? Wk :
                     (blockIdx.z == 2) ? Wv : Wo;
    __half* WT = (__half*)g_Wh[blockIdx.z];
    const int tx = threadIdx.x & 31;
    const int ty = threadIdx.x >> 5;
    const int n0 = blockIdx.x * 32;
    const int k0 = blockIdx.y * 32;
#pragma unroll
    for (int j = 0; j < 32; j += 8)
        t[ty + j][tx] = W[(size_t)(k0 + ty + j) * Ee + n0 + tx];
    __syncthreads();
#pragma unroll
    for (int j = 0; j < 32; j += 8) {
        int k = k0 + tx;
        int kk = knew(k >> 1) * 2 + (k & 1);
        WT[(size_t)(n0 + ty + j) * Ee + kk] = __float2half_rn(t[tx][ty + j]);
    }
}

__global__ __launch_bounds__(256) void conv_wg1(const float* __restrict__ Wg1)
{
    __shared__ float t[32][33];
    __half* WT = (__half*)g_Wg1h;
    const int tx = threadIdx.x & 31;
    const int ty = threadIdx.x >> 5;
    const int n0 = blockIdx.x * 32;
    const int k0 = blockIdx.y * 32;
#pragma unroll
    for (int j = 0; j < 32; j += 8)
        t[ty + j][tx] = Wg1[(size_t)(k0 + ty + j) * Dd + n0 + tx];
    __syncthreads();
#pragma unroll
    for (int j = 0; j < 32; j += 8) {
        int k = k0 + tx;
        int kk = knew(k >> 1) * 2 + (k & 1);
        WT[(size_t)(n0 + ty + j) * Ee + kk] = __float2half_rn(t[tx][ty + j]);
    }
}

// ============================================================
// fp16 mma.sync GEMM, 128 threads / 4 warps (2m x 2n),
// 4-stage cp.async pipeline, K-permuted LDS.128 fragments.
// ============================================================
#define RU 16
#define STGH 4

template<int NB>
__device__ __forceinline__ void gemm_core_f16(
    const uint32_t* __restrict__ A, const uint32_t* __restrict__ Bm,
    float* __restrict__ C, int brow, int bcol, int act, int ldc)
{
    constexpr int NI = NB / 16;
    extern __shared__ uint32_t smem[];
    const int stageA = 128 * RU;
    const int stageB = NB * RU;
    uint32_t* As0 = smem;
    uint32_t* Bs0 = smem + STGH * stageA;

    const int tid  = threadIdx.x;
    const int wid  = tid >> 5;
    const int lane = tid & 31;
    const int g = lane >> 2, t = lane & 3;
    const int wm = (wid & 1) * 64;
    const int wn = (wid >> 1) * (NB / 2);

    const int r0 = tid >> 2, p0 = (tid & 3) * 4;
    const uint32_t* Ag = A + (size_t)(brow + r0) * 512 + p0;
    const uint32_t* Bg = Bm + (size_t)(bcol + r0) * 512 + p0;
    const uint32_t dA = s2u(As0 + r0 * RU + p0);
    const uint32_t dB = s2u(Bs0 + r0 * RU + p0);

    const uint32_t sAb = stageA * 4;
    const uint32_t sBb = stageB * 4;

    uint32_t aAdr[4];
#pragma unroll
    for (int mi = 0; mi < 4; mi++)
        aAdr[mi] = s2u(As0 + (wm + mi * 16 + g) * RU + 4 * t);
    uint32_t bAdr[NI];
#pragma unroll
    for (int ni = 0; ni < NI; ni++)
        bAdr[ni] = s2u(Bs0 + (wn + ni * 8 + g) * RU + 4 * t);

    float acc[4][NI][4];
#pragma unroll
    for (int mi = 0; mi < 4; mi++)
#pragma unroll
        for (int ni = 0; ni < NI; ni++)
#pragma unroll
            for (int j = 0; j < 4; j++) acc[mi][ni][j] = 0.0f;

#pragma unroll
    for (int p = 0; p < 3; p++) {
#pragma unroll
        for (int i = 0; i < 4; i++)
            CP16(dA + p * sAb + i * 2048, Ag + p * 16 + (size_t)i * (32 * 512));
#pragma unroll
        for (int i = 0; i < NB / 32; i++)
            CP16(dB + p * sBb + i * 2048, Bg + p * 16 + (size_t)i * (32 * 512));
        CP_COMMIT();
    }

    const uint32_t* agp = Ag + 48;
    const uint32_t* bgp = Bg + 48;

#pragma unroll 1
    for (int cc = 0; cc < 32; cc += 4) {
#pragma unroll
        for (int s = 0; s < 4; s++) {
            const int c = cc + s;
            CP_WAIT2();
            __syncthreads();

            if (c < 29) {
                const uint32_t pofA = ((s + 3) & 3) * sAb;
                const uint32_t pofB = ((s + 3) & 3) * sBb;
#pragma unroll
                for (int i = 0; i < 4; i++)
                    CP16(dA + pofA + i * 2048, agp + (size_t)i * (32 * 512));
#pragma unroll
                for (int i = 0; i < NB / 32; i++)
                    CP16(dB + pofB + i * 2048, bgp + (size_t)i * (32 * 512));
                CP_COMMIT();
                agp += 16; bgp += 16;
            }

            const uint32_t offA = s * sAb;
            const uint32_t offB = s * sBb;

            uint4 Af[4][2];
#pragma unroll
            for (int mi = 0; mi < 4; mi++) {
                Af[mi][0] = lds128(aAdr[mi] + offA);
                Af[mi][1] = lds128(aAdr[mi] + offA + 512);
            }
            uint4 Bf[NI];
#pragma unroll
            for (int ni = 0; ni < NI; ni++)
                Bf[ni] = lds128(bAdr[ni] + offB);

#pragma unroll
            for (int mi = 0; mi < 4; mi++)
#pragma unroll
                for (int ni = 0; ni < NI; ni++)
                    mma_f16(acc[mi][ni],
                            Af[mi][0].x, Af[mi][1].x, Af[mi][0].y, Af[mi][1].y,
                            Bf[ni].x, Bf[ni].y);
#pragma unroll
            for (int mi = 0; mi < 4; mi++)
#pragma unroll
                for (int ni = 0; ni < NI; ni++)
                    mma_f16(acc[mi][ni],
                            Af[mi][0].z, Af[mi][1].z, Af[mi][0].w, Af[mi][1].w,
                            Bf[ni].z, Bf[ni].w);
        }
    }

#pragma unroll
    for (int mi = 0; mi < 4; mi++) {
        const int r = brow + wm + mi * 16 + g;
#pragma unroll
        for (int ni = 0; ni < NI; ni++) {
            const int col = bcol + wn + ni * 8 + 2 * t;
            float v0 = acc[mi][ni][0], v1 = acc[mi][ni][1];
            float v2 = acc[mi][ni][2], v3 = acc[mi][ni][3];
            if (act) { v0 = silu_f(v0); v1 = silu_f(v1); v2 = silu_f(v2); v3 = silu_f(v3); }
            float2 lo; lo.x = v0; lo.y = v1;
            float2 hi; hi.x = v2; hi.y = v3;
            *(float2*)(C + (size_t)r * ldc + col) = lo;
            *(float2*)(C + (size_t)(r + 8) * ldc + col) = hi;
        }
    }
}

#define GEMM_SMEM_BIG (STGH * (128*RU + 128*RU) * 4)
#define GEMM_SMEM_G1  (STGH * (128*RU + 64*RU) * 4)

__global__ __launch_bounds__(128) void gemm_qkv_f16()
{
    float* C = (blockIdx.z == 0) ? g_q : (blockIdx.z == 1) ? g_k : g_v;
    gemm_core_f16<128>(g_xh, g_Wh[blockIdx.z], C,
                       blockIdx.y * 128, blockIdx.x * 128, 1, Ee);
}

__global__ __launch_bounds__(128) void gemm_out_f16(float* __restrict__ C)
{
    gemm_core_f16<128>(g_uh, g_Wh[3], C,
                       blockIdx.y * 128, blockIdx.x * 128, 0, Ee);
}

__global__ __launch_bounds__(128) void gemm_g1_f16()
{
    gemm_core_f16<64>(g_xh, g_Wg1h, g_g1,
                      blockIdx.x * 128, 0, 0, Dd);
}

// ============================================================
// gd = g1 @ Wg2  (fp32 FFMA). M=16384, N=1024, K=64.
// ============================================================
__global__ __launch_bounds__(256) void sgemm_gd(const float* __restrict__ Wg2)
{
    __shared__ float As[2][8][128];
    __shared__ float Bs[2][8][128];

    const float* A = g_g1;
    const int N = Ee, K = Dd;

    const int tid  = threadIdx.x;
    const int tx   = tid & 15;
    const int ty   = tid >> 4;
    const int brow = blockIdx.y * 128;
    const int bcol = blockIdx.x * 128;

    const int arow = tid >> 1;
    const int acol = (tid & 1) * 4;
    const int bkr  = tid >> 5;
    const int bcl  = (tid & 31) * 4;

    const float* Ap = A + (size_t)(brow + arow) * K + acol;
    const float* Bp = Wg2 + (size_t)bkr * N + bcol + bcl;

    float4 ar = *(const float4*)Ap;
    float4 br = *(const float4*)Bp;
    As[0][acol + 0][arow] = ar.x;
    As[0][acol + 1][arow] = ar.y;
    As[0][acol + 2][arow] = ar.z;
    As[0][acol + 3][arow] = ar.w;
    *(float4*)&Bs[0][bkr][bcl] = br;
    __syncthreads();

    float acc[8][8];
#pragma unroll
    for (int i = 0; i < 8; i++)
#pragma unroll
        for (int j = 0; j < 8; j++) acc[i][j] = 0.0f;

    int buf = 0;
    for (int k0 = 8; k0 <= K; k0 += 8) {
        if (k0 < K) {
            ar = *(const float4*)(Ap + k0);
            br = *(const float4*)(Bp + (size_t)k0 * N);
        }
#pragma unroll
        for (int kk = 0; kk < 8; kk++) {
            float af[8], bf[8];
            *(float4*)&af[0] = *(float4*)&As[buf][kk][ty * 8];
            *(float4*)&af[4] = *(float4*)&As[buf][kk][ty * 8 + 4];
            *(float4*)&bf[0] = *(float4*)&Bs[buf][kk][tx * 8];
            *(float4*)&bf[4] = *(float4*)&Bs[buf][kk][tx * 8 + 4];
#pragma unroll
            for (int i = 0; i < 8; i++)
#pragma unroll
                for (int j = 0; j < 8; j++)
                    acc[i][j] = fmaf(af[i], bf[j], acc[i][j]);
        }
        if (k0 < K) {
            buf ^= 1;
            As[buf][acol + 0][arow] = ar.x;
            As[buf][acol + 1][arow] = ar.y;
            As[buf][acol + 2][arow] = ar.z;
            As[buf][acol + 3][arow] = ar.w;
            *(float4*)&Bs[buf][bkr][bcl] = br;
            __syncthreads();
        }
    }

#pragma unroll
    for (int i = 0; i < 8; i++) {
        float* Cp = g_gd + (size_t)(brow + ty * 8 + i) * N + bcol + tx * 8;
#pragma unroll
        for (int j0 = 0; j0 < 8; j0 += 4) {
            float4 o;
            o.x = acc[i][j0 + 0];
            o.y = acc[i][j0 + 1];
            o.z = acc[i][j0 + 2];
            o.w = acc[i][j0 + 3];
            *(float4*)(Cp + j0) = o;
        }
    }
}

// ============================================================
// Intra-chunk attention + per-chunk kv contribution A_c (fp32)
// ============================================================
#define SM_QT   0
#define SM_KT   (64*132)
#define SM_VS   (2*64*132)
#define SM_SS   (2*64*132 + 128*68)
#define SM_LAM  (2*64*132 + 128*68 + 128*129)
#define SMEM_INTRA_FLOATS (2*64*132 + 128*68 + 128*129 + 128)

__global__ __launch_bounds__(256) void attn_intra(
    const float* __restrict__ q, const float* __restrict__ k,
    const float* __restrict__ v)
{
    extern __shared__ float sm[];
    float* qT  = sm + SM_QT;
    float* kT  = sm + SM_KT;
    float* vs  = sm + SM_VS;
    float* Ss  = sm + SM_SS;
    float* lamk = sm + SM_LAM;

    const int c = blockIdx.x, h = blockIdx.y, b = blockIdx.z;
    const int tid = threadIdx.x;
    const float s = head_slope(h);
    const size_t base = ((size_t)b * Nn + (size_t)c * Cc) * Ee + (size_t)h * Dd;

#pragma unroll
    for (int t = 0; t < 8; t++) {
        int e = tid + t * 256;
        int row = e >> 4;
        int d4 = (e & 15) * 4;
        const size_t g = base + (size_t)row * Ee + d4;
        float4 qv = *(const float4*)(q + g);
        qT[(d4 + 0) * 132 + row] = qv.x;
        qT[(d4 + 1) * 132 + row] = qv.y;
        qT[(d4 + 2) * 132 + row] = qv.z;
        qT[(d4 + 3) * 132 + row] = qv.w;
        float4 kv4 = *(const float4*)(k + g);
        kT[(d4 + 0) * 132 + row] = kv4.x;
        kT[(d4 + 1) * 132 + row] = kv4.y;
        kT[(d4 + 2) * 132 + row] = kv4.z;
        kT[(d4 + 3) * 132 + row] = kv4.w;
        *(float4*)&vs[row * 68 + d4] = *(const float4*)(v + g);
    }
    if (tid < 128) lamk[tid] = expf(-s * (float)(Cc - 1 - tid));
    __syncthreads();

    const int tx = tid & 15, ty = tid >> 4;

    float acc[8][8];
#pragma unroll
    for (int i = 0; i < 8; i++)
#pragma unroll
        for (int j = 0; j < 8; j++) acc[i][j] = 0.0f;

    for (int d = 0; d < 64; d++) {
        float af[8], bf[8];
        *(float4*)&af[0] = *(float4*)&qT[d * 132 + ty * 8];
        *(float4*)&af[4] = *(float4*)&qT[d * 132 + ty * 8 + 4];
        *(float4*)&bf[0] = *(float4*)&kT[d * 132 + tx * 8];
        *(float4*)&bf[4] = *(float4*)&kT[d * 132 + tx * 8 + 4];
#pragma unroll
        for (int i = 0; i < 8; i++)
#pragma unroll
            for (int j = 0; j < 8; j++)
                acc[i][j] = fmaf(af[i], bf[j], acc[i][j]);
    }
#pragma unroll
    for (int ii = 0; ii < 8; ii++) {
        int i = ty * 8 + ii;
#pragma unroll
        for (int jj = 0; jj < 8; jj++) {
            int j = tx * 8 + jj;
            float val = 0.0f;
            if (i >= j) val = acc[ii][jj] * expf(-s * (float)(i - j));
            Ss[i * 129 + j] = val;
        }
    }
    __syncthreads();

    float oc[8][4];
#pragma unroll
    for (int i = 0; i < 8; i++)
#pragma unroll
        for (int j = 0; j < 4; j++) oc[i][j] = 0.0f;

    for (int j = 0; j < 128; j++) {
        float bv[4];
        *(float4*)bv = *(float4*)&vs[j * 68 + tx * 4];
#pragma unroll
        for (int ii = 0; ii < 8; ii++) {
            float a = Ss[(ty * 8 + ii) * 129 + j];
#pragma unroll
            for (int dd = 0; dd < 4; dd++)
                oc[ii][dd] = fmaf(a, bv[dd], oc[ii][dd]);
        }
    }
#pragma unroll
    for (int ii = 0; ii < 8; ii++) {
        float4 o;
        o.x = oc[ii][0]; o.y = oc[ii][1]; o.z = oc[ii][2]; o.w = oc[ii][3];
        *(float4*)(g_o + base + (size_t)(ty * 8 + ii) * Ee + tx * 4) = o;
    }

    float ac[4][4];
#pragma unroll
    for (int i = 0; i < 4; i++)
#pragma unroll
        for (int j = 0; j < 4; j++) ac[i][j] = 0.0f;

    const int dr = ty * 4;
    for (int j = 0; j < 128; j++) {
        float lam = lamk[j];
        float bv[4];
        *(float4*)bv = *(float4*)&vs[j * 68 + tx * 4];
#pragma unroll
        for (int i = 0; i < 4; i++) {
            float a = kT[(dr + i) * 132 + j] * lam;
#pragma unroll
            for (int e2 = 0; e2 < 4; e2++)
                ac[i][e2] = fmaf(a, bv[e2], ac[i][e2]);
        }
    }
    float* Ab = g_A + ((((size_t)b * Hh + h) * NCk + c) * (Dd * Dd));
#pragma unroll
    for (int i = 0; i < 4; i++) {
        float4 o;
        o.x = ac[i][0]; o.y = ac[i][1]; o.z = ac[i][2]; o.w = ac[i][3];
        *(float4*)&Ab[(dr + i) * Dd + tx * 4] = o;
    }
}

// ============================================================
// kv prefix scan: one (b,h,element) chain per thread
// ============================================================
__global__ __launch_bounds__(256) void kv_scan()
{
    const int gidx = blockIdx.x * 256 + threadIdx.x;
    const int bh = gidx >> 12;
    const int e  = gidx & 4095;
    const int h  = bh & 15;
    const float s = head_slope(h);
    const float lamc = expf(-s * (float)Cc);

    size_t off = (size_t)bh * NCk * (Dd * Dd) + e;
    float kv = 0.0f;
#pragma unroll 4
    for (int c = 0; c < NCk; c++) {
        g_kv[off] = kv;
        kv = fmaf(lamc, kv, g_A[off]);
        off += Dd * Dd;
    }
}

// ============================================================
// Inter-chunk: o += lam_q[i] * (q @ kv_prefix)   [skips chunk 0]
// ============================================================
#define SMEM_INTER_FLOATS (128*68 + 64*68)

__global__ __launch_bounds__(256) void attn_inter(const float* __restrict__ q)
{
    extern __shared__ float smf[];
    float* qs  = smf;
    float* kvs = smf + 128 * 68;

    const int c = blockIdx.x + 1;       // chunk 0 has zero kv prefix
    const int h = blockIdx.y, b = blockIdx.z;
    const int tid = threadIdx.x;
    const float s = head_slope(h);
    const size_t base = ((size_t)b * Nn + (size_t)c * Cc) * Ee + (size_t)h * Dd;

#pragma unroll
    for (int t = 0; t < 8; t++) {
        int e = tid + t * 256;
        int row = e >> 4;
        int d4 = (e & 15) * 4;
        *(float4*)&qs[row * 68 + d4] = *(const float4*)(q + base + (size_t)row * Ee + d4);
    }
    const float* kvp = g_kv + (((size_t)b * Hh + h) * NCk + c) * (Dd * Dd);
#pragma unroll
    for (int t = 0; t < 4; t++) {
        int e = tid + t * 256;
        int row = e >> 4;
        int d4 = (e & 15) * 4;
        *(float4*)&kvs[row * 68 + d4] = *(const float4*)(kvp + row * Dd + d4);
    }
    __syncthreads();

    const int tx = tid & 15, ty = tid >> 4;
    float oc[8][4];
#pragma unroll
    for (int i = 0; i < 8; i++)
#pragma unroll
        for (int j = 0; j < 4; j++) oc[i][j] = 0.0f;

    for (int e2 = 0; e2 < 64; e2++) {
        float bv[4];
        *(float4*)bv = *(float4*)&kvs[e2 * 68 + tx * 4];
#pragma unroll
        for (int ii = 0; ii < 8; ii++) {
            float a = qs[(ty * 8 + ii) * 68 + e2];
#pragma unroll
            for (int dd = 0; dd < 4; dd++)
                oc[ii][dd] = fmaf(a, bv[dd], oc[ii][dd]);
        }
    }
#pragma unroll
    for (int ii = 0; ii < 8; ii++) {
        int i = ty * 8 + ii;
        float lamq = expf(-s * (float)(i + 1));
        float* op = g_o + base + (size_t)i * Ee + tx * 4;
        float4 prev = *(float4*)op;
        prev.x = fmaf(lamq, oc[ii][0], prev.x);
        prev.y = fmaf(lamq, oc[ii][1], prev.y);
        prev.z = fmaf(lamq, oc[ii][2], prev.z);
        prev.w = fmaf(lamq, oc[ii][3], prev.w);
        *(float4*)op = prev;
    }
}

// ============================================================
// LayerNorm + sigmoid(gd) * -> g_uh (half, K-PERMUTED)
// Warp-per-row reductions: no block barriers after initial load.
// ============================================================
__global__ __launch_bounds__(256) void ln_gate(
    const float* __restrict__ gamma, const float* __restrict__ beta)
{
    __shared__ float os[8 * 1024];

    const int tid = threadIdx.x;
    const size_t row0 = (size_t)blockIdx.x * 8;

#pragma unroll
    for (int t = 0; t < 8; t++) {
        int e = tid + t * 256;
        int r = e >> 8;
        int c4 = (e & 255) * 4;
        *(float4*)&os[r * 1024 + c4] = *(const float4*)(g_o + (row0 + r) * 1024 + c4);
    }
    __syncthreads();

    const int lane = tid & 31, wid = tid >> 5;
    const int r = wid;                    // warp w owns row w

    // mean: 32 elems per lane
    float sum = 0.0f;
#pragma unroll
    for (int i = 0; i < 32; i++) sum += os[r * 1024 + lane + i * 32];
#pragma unroll
    for (int o = 16; o; o >>= 1) sum += __shfl_xor_sync(0xffffffffu, sum, o);
    const float mu = sum * (1.0f / 1024.0f);

    // variance (two-pass)
    float sq = 0.0f;
#pragma unroll
    for (int i = 0; i < 32; i++) {
        float d = os[r * 1024 + lane + i * 32] - mu;
        sq = fmaf(d, d, sq);
    }
#pragma unroll
    for (int o = 16; o; o >>= 1) sq += __shfl_xor_sync(0xffffffffu, sq, o);
    const float rs = rsqrtf(sq * (1.0f / 1024.0f) + 1e-5f);

    const int cbase = lane * 4;
#pragma unroll
    for (int t = 0; t < 8; t++) {
        int col = cbase + t * 128;
        float4 ov = *(float4*)&os[r * 1024 + col];
        float4 gd = *(const float4*)(g_gd + (row0 + r) * 1024 + col);
        float4 gm = *(const float4*)(gamma + col);
        float4 bt = *(const float4*)(beta + col);
        float ux = (fmaf((ov.x - mu) * rs, gm.x, bt.x)) * (1.0f / (1.0f + expf(-gd.x)));
        float uy = (fmaf((ov.y - mu) * rs, gm.y, bt.y)) * (1.0f / (1.0f + expf(-gd.y)));
        float uz = (fmaf((ov.z - mu) * rs, gm.z, bt.z)) * (1.0f / (1.0f + expf(-gd.z)));
        float uw = (fmaf((ov.w - mu) * rs, gm.w, bt.w)) * (1.0f / (1.0f + expf(-gd.w)));
        int o0 = col >> 1;
        size_t rb = (row0 + r) * 512;
        g_uh[rb + knew(o0)]     = packh2(ux, uy);
        g_uh[rb + knew(o0 + 1)] = packh2(uz, uw);
    }
}

// ============================================================
// host launch
// ============================================================
extern "C" void kernel_launch(void* const* d_in, const int* in_sizes, int n_in,
                              void* d_out, int out_size)
{
    const float* x     = (const float*)d_in[0];
    const float* Wq    = (const float*)d_in[1];
    const float* Wk    = (const float*)d_in[2];
    const float* Wv    = (const float*)d_in[3];
    const float* Wo    = (const float*)d_in[4];
    const float* gamma = (const float*)d_in[5];
    const float* beta  = (const float*)d_in[6];
    const float* Wg1   = (const float*)d_in[7];
    const float* Wg2   = (const float*)d_in[8];
    float* out = (float*)d_out;

    static bool init_done = false;
    static float *qp, *kp, *vp;
    if (!init_done) {
        cudaGetSymbolAddress((void**)&qp, g_q);
        cudaGetSymbolAddress((void**)&kp, g_k);
        cudaGetSymbolAddress((void**)&vp, g_v);
        cudaFuncSetAttribute(attn_intra, cudaFuncAttributeMaxDynamicSharedMemorySize,
                             SMEM_INTRA_FLOATS * (int)sizeof(float));
        cudaFuncSetAttribute(attn_inter, cudaFuncAttributeMaxDynamicSharedMemorySize,
                             SMEM_INTER_FLOATS * (int)sizeof(float));
        cudaFuncSetAttribute(gemm_qkv_f16, cudaFuncAttributeMaxDynamicSharedMemorySize,
                             GEMM_SMEM_BIG);
        cudaFuncSetAttribute(gemm_out_f16, cudaFuncAttributeMaxDynamicSharedMemorySize,
                             GEMM_SMEM_BIG);
        cudaFuncSetAttribute(gemm_g1_f16, cudaFuncAttributeMaxDynamicSharedMemorySize,
                             GEMM_SMEM_G1);
        init_done = true;
    }

    const int smem_intra = SMEM_INTRA_FLOATS * (int)sizeof(float);
    const int smem_inter = SMEM_INTER_FLOATS * (int)sizeof(float);

    dim3 blk(256);
    dim3 blk128(128);

    conv_x<<<4096, blk>>>(x);
    conv_wt<<<dim3(32, 32, 4), blk>>>(Wq, Wk, Wv, Wo);
    conv_wg1<<<dim3(2, 32), blk>>>(Wg1);

    gemm_qkv_f16<<<dim3(Ee / 128, Mm / 128, 3), blk128, GEMM_SMEM_BIG>>>();
    gemm_g1_f16<<<Mm / 128, blk128, GEMM_SMEM_G1>>>();
    sgemm_gd<<<dim3(Ee / 128, Mm / 128), blk>>>(Wg2);

    attn_intra<<<dim3(NCk, Hh, Bb), blk, smem_intra>>>(qp, kp, vp);
    kv_scan<<<512, blk>>>();
    attn_inter<<<dim3(NCk - 1, Hh, Bb), blk, smem_inter>>>(qp);

    ln_gate<<<Mm / 8, blk>>>(gamma, beta);

    gemm_out_f16<<<dim3(Ee / 128, Mm / 128), blk128, GEMM_SMEM_BIG>>>(out);
}

// round 17
// speedup vs baseline: 1.0533x; 1.0206x over previous
#include <cuda_runtime.h>
#include <cuda_fp16.h>
#include <math.h>
#include <stdint.h>

// ---------------- problem constants ----------------
#define Bb   2
#define Nn   8192
#define Ee   1024
#define Hh   16
#define Dd   64
#define Cc   128
#define NCk  64
#define Mm   (Bb*Nn)

// ---------------- device scratch ----------------
__device__ float g_q[(size_t)Mm*Ee];
__device__ float g_k[(size_t)Mm*Ee];
__device__ float g_v[(size_t)Mm*Ee];
__device__ float g_o[(size_t)Mm*Ee];
__device__ float g_A [(size_t)Bb*Hh*NCk*Dd*Dd];
__device__ float g_kv[(size_t)Bb*Hh*NCk*Dd*Dd];
__device__ float g_g1[(size_t)Mm*Dd];
__device__ float g_gd[(size_t)Mm*Ee];             // gate pre-sigmoid = g1 @ Wg2
__device__ uint32_t g_xh[(size_t)Mm*Ee/2];        // x half2, [m][k] K-PERMUTED
__device__ uint32_t g_uh[(size_t)Mm*Ee/2];        // LN-gate out half2, K-PERMUTED
__device__ uint32_t g_Wh[4][(size_t)Ee*Ee/2];     // W^T half2: [n][k] K-PERMUTED
__device__ uint32_t g_Wg1h[(size_t)Dd*Ee/2];      // Wg1^T half2: [n=64][k] K-PERMUTED

// K-permutation within each 16-uint32 (32-half) block:
//   new[4j+i] = orig[j+4i]  (j,i in 0..3)
__device__ __forceinline__ int knew(int o) {
    return (o & ~15) + 4 * (o & 3) + ((o & 15) >> 2);
}

__device__ __forceinline__ float head_slope(int h) {
    return exp2f(-0.5f * (float)(h + 1)) * 1.00001f;
}
__device__ __forceinline__ float silu_f(float v) { return v / (1.0f + expf(-v)); }
__device__ __forceinline__ uint32_t s2u(const void* p) {
    return (uint32_t)__cvta_generic_to_shared(p);
}
__device__ __forceinline__ uint32_t packh2(float a, float b) {
    __half2 h = __floats2half2_rn(a, b);
    return *(uint32_t*)&h;
}

#define CP16(dst, src) \
    asm volatile("cp.async.cg.shared.global [%0], [%1], 16;" :: "r"(dst), "l"(src) : "memory")
#define CP_COMMIT() asm volatile("cp.async.commit_group;" ::: "memory")
#define CP_WAIT2()  asm volatile("cp.async.wait_group 2;" ::: "memory")

__device__ __forceinline__ void mma_f16(
    float c[4], uint32_t a0, uint32_t a1, uint32_t a2, uint32_t a3,
    uint32_t b0, uint32_t b1)
{
    asm volatile(
        "mma.sync.aligned.m16n8k16.row.col.f32.f16.f16.f32 "
        "{%0,%1,%2,%3}, {%4,%5,%6,%7}, {%8,%9}, {%0,%1,%2,%3};"
        : "+f"(c[0]), "+f"(c[1]), "+f"(c[2]), "+f"(c[3])
        : "r"(a0), "r"(a1), "r"(a2), "r"(a3), "r"(b0), "r"(b1));
}

__device__ __forceinline__ uint4 lds128(uint32_t addr)
{
    uint4 r;
    asm volatile("ld.shared.v4.b32 {%0,%1,%2,%3}, [%4];"
                 : "=r"(r.x), "=r"(r.y), "=r"(r.z), "=r"(r.w) : "r"(addr));
    return r;
}

// ============================================================
// Conversion kernels (emit K-PERMUTED layouts)
// ============================================================
__global__ __launch_bounds__(256) void conv_x(const float* __restrict__ x)
{
    size_t f = (size_t)(blockIdx.x * 256 + threadIdx.x);
    const size_t n4 = (size_t)Mm * Ee / 4;
    const size_t stride = (size_t)gridDim.x * 256;
    for (; f < n4; f += stride) {
        float4 v = ((const float4*)x)[f];
        int o0 = (int)(f * 2) & 511;
        size_t rowbase = (f * 2) & ~(size_t)511;
        g_xh[rowbase + knew(o0)]     = packh2(v.x, v.y);
        g_xh[rowbase + knew(o0 + 1)] = packh2(v.z, v.w);
    }
}

__global__ __launch_bounds__(256) void conv_wt(
    const float* __restrict__ Wq, const float* __restrict__ Wk,
    const float* __restrict__ Wv, const float* __restrict__ Wo)
{
    __shared__ float t[32][33];
    const float* W = (blockIdx.z == 0) ? Wq : (blockIdx.z == 1) ? Wk :
                     (blockIdx.z == 2) ? Wv : Wo;
    __half* WT = (__half*)g_Wh[blockIdx.z];
    const int tx = threadIdx.x & 31;
    const int ty = threadIdx.x >> 5;
    const int n0 = blockIdx.x * 32;
    const int k0 = blockIdx.y * 32;
#pragma unroll
    for (int j = 0; j < 32; j += 8)
        t[ty + j][tx] = W[(size_t)(k0 + ty + j) * Ee + n0 + tx];
    __syncthreads();
#pragma unroll
    for (int j = 0; j < 32; j += 8) {
        int k = k0 + tx;
        int kk = knew(k >> 1) * 2 + (k & 1);
        WT[(size_t)(n0 + ty + j) * Ee + kk] = __float2half_rn(t[tx][ty + j]);
    }
}

__global__ __launch_bounds__(256) void conv_wg1(const float* __restrict__ Wg1)
{
    __shared__ float t[32][33];
    __half* WT = (__half*)g_Wg1h;
    const int tx = threadIdx.x & 31;
    const int ty = threadIdx.x >> 5;
    const int n0 = blockIdx.x * 32;
    const int k0 = blockIdx.y * 32;
#pragma unroll
    for (int j = 0; j < 32; j += 8)
        t[ty + j][tx] = Wg1[(size_t)(k0 + ty + j) * Dd + n0 + tx];
    __syncthreads();
#pragma unroll
    for (int j = 0; j < 32; j += 8) {
        int k = k0 + tx;
        int kk = knew(k >> 1) * 2 + (k & 1);
        WT[(size_t)(n0 + ty + j) * Ee + kk] = __float2half_rn(t[tx][ty + j]);
    }
}

// ============================================================
// fp16 mma.sync GEMM, 128 threads / 4 warps (2m x 2n),
// 4-stage cp.async pipeline, K-permuted LDS.128 fragments.
// ============================================================
#define RU 16
#define STGH 4

template<int NB>
__device__ __forceinline__ void gemm_core_f16(
    const uint32_t* __restrict__ A, const uint32_t* __restrict__ Bm,
    float* __restrict__ C, int brow, int bcol, int act, int ldc)
{
    constexpr int NI = NB / 16;
    extern __shared__ uint32_t smem[];
    const int stageA = 128 * RU;
    const int stageB = NB * RU;
    uint32_t* As0 = smem;
    uint32_t* Bs0 = smem + STGH * stageA;

    const int tid  = threadIdx.x;
    const int wid  = tid >> 5;
    const int lane = tid & 31;
    const int g = lane >> 2, t = lane & 3;
    const int wm = (wid & 1) * 64;
    const int wn = (wid >> 1) * (NB / 2);

    const int r0 = tid >> 2, p0 = (tid & 3) * 4;
    const uint32_t* Ag = A + (size_t)(brow + r0) * 512 + p0;
    const uint32_t* Bg = Bm + (size_t)(bcol + r0) * 512 + p0;
    const uint32_t dA = s2u(As0 + r0 * RU + p0);
    const uint32_t dB = s2u(Bs0 + r0 * RU + p0);

    const uint32_t sAb = stageA * 4;
    const uint32_t sBb = stageB * 4;

    uint32_t aAdr[4];
#pragma unroll
    for (int mi = 0; mi < 4; mi++)
        aAdr[mi] = s2u(As0 + (wm + mi * 16 + g) * RU + 4 * t);
    uint32_t bAdr[NI];
#pragma unroll
    for (int ni = 0; ni < NI; ni++)
        bAdr[ni] = s2u(Bs0 + (wn + ni * 8 + g) * RU + 4 * t);

    float acc[4][NI][4];
#pragma unroll
    for (int mi = 0; mi < 4; mi++)
#pragma unroll
        for (int ni = 0; ni < NI; ni++)
#pragma unroll
            for (int j = 0; j < 4; j++) acc[mi][ni][j] = 0.0f;

#pragma unroll
    for (int p = 0; p < 3; p++) {
#pragma unroll
        for (int i = 0; i < 4; i++)
            CP16(dA + p * sAb + i * 2048, Ag + p * 16 + (size_t)i * (32 * 512));
#pragma unroll
        for (int i = 0; i < NB / 32; i++)
            CP16(dB + p * sBb + i * 2048, Bg + p * 16 + (size_t)i * (32 * 512));
        CP_COMMIT();
    }

    const uint32_t* agp = Ag + 48;
    const uint32_t* bgp = Bg + 48;

#pragma unroll 1
    for (int cc = 0; cc < 32; cc += 4) {
#pragma unroll
        for (int s = 0; s < 4; s++) {
            const int c = cc + s;
            CP_WAIT2();
            __syncthreads();

            if (c < 29) {
                const uint32_t pofA = ((s + 3) & 3) * sAb;
                const uint32_t pofB = ((s + 3) & 3) * sBb;
#pragma unroll
                for (int i = 0; i < 4; i++)
                    CP16(dA + pofA + i * 2048, agp + (size_t)i * (32 * 512));
#pragma unroll
                for (int i = 0; i < NB / 32; i++)
                    CP16(dB + pofB + i * 2048, bgp + (size_t)i * (32 * 512));
                CP_COMMIT();
                agp += 16; bgp += 16;
            }

            const uint32_t offA = s * sAb;
            const uint32_t offB = s * sBb;

            uint4 Af[4][2];
#pragma unroll
            for (int mi = 0; mi < 4; mi++) {
                Af[mi][0] = lds128(aAdr[mi] + offA);
                Af[mi][1] = lds128(aAdr[mi] + offA + 512);
            }
            uint4 Bf[NI];
#pragma unroll
            for (int ni = 0; ni < NI; ni++)
                Bf[ni] = lds128(bAdr[ni] + offB);

#pragma unroll
            for (int mi = 0; mi < 4; mi++)
#pragma unroll
                for (int ni = 0; ni < NI; ni++)
                    mma_f16(acc[mi][ni],
                            Af[mi][0].x, Af[mi][1].x, Af[mi][0].y, Af[mi][1].y,
                            Bf[ni].x, Bf[ni].y);
#pragma unroll
            for (int mi = 0; mi < 4; mi++)
#pragma unroll
                for (int ni = 0; ni < NI; ni++)
                    mma_f16(acc[mi][ni],
                            Af[mi][0].z, Af[mi][1].z, Af[mi][0].w, Af[mi][1].w,
                            Bf[ni].z, Bf[ni].w);
        }
    }

#pragma unroll
    for (int mi = 0; mi < 4; mi++) {
        const int r = brow + wm + mi * 16 + g;
#pragma unroll
        for (int ni = 0; ni < NI; ni++) {
            const int col = bcol + wn + ni * 8 + 2 * t;
            float v0 = acc[mi][ni][0], v1 = acc[mi][ni][1];
            float v2 = acc[mi][ni][2], v3 = acc[mi][ni][3];
            if (act) { v0 = silu_f(v0); v1 = silu_f(v1); v2 = silu_f(v2); v3 = silu_f(v3); }
            float2 lo; lo.x = v0; lo.y = v1;
            float2 hi; hi.x = v2; hi.y = v3;
            *(float2*)(C + (size_t)r * ldc + col) = lo;
            *(float2*)(C + (size_t)(r + 8) * ldc + col) = hi;
        }
    }
}

#define GEMM_SMEM_BIG (STGH * (128*RU + 128*RU) * 4)
#define GEMM_SMEM_G1  (STGH * (128*RU + 64*RU) * 4)

__global__ __launch_bounds__(128) void gemm_qkv_f16()
{
    float* C = (blockIdx.z == 0) ? g_q : (blockIdx.z == 1) ? g_k : g_v;
    gemm_core_f16<128>(g_xh, g_Wh[blockIdx.z], C,
                       blockIdx.y * 128, blockIdx.x * 128, 1, Ee);
}

__global__ __launch_bounds__(128) void gemm_out_f16(float* __restrict__ C)
{
    gemm_core_f16<128>(g_uh, g_Wh[3], C,
                       blockIdx.y * 128, blockIdx.x * 128, 0, Ee);
}

__global__ __launch_bounds__(128) void gemm_g1_f16()
{
    gemm_core_f16<64>(g_xh, g_Wg1h, g_g1,
                      blockIdx.x * 128, 0, 0, Dd);
}

// ============================================================
// gd = g1 @ Wg2  (fp32 FFMA). M=16384, N=1024, K=64.
// ============================================================
__global__ __launch_bounds__(256) void sgemm_gd(const float* __restrict__ Wg2)
{
    __shared__ float As[2][8][128];
    __shared__ float Bs[2][8][128];

    const float* A = g_g1;
    const int N = Ee, K = Dd;

    const int tid  = threadIdx.x;
    const int tx   = tid & 15;
    const int ty   = tid >> 4;
    const int brow = blockIdx.y * 128;
    const int bcol = blockIdx.x * 128;

    const int arow = tid >> 1;
    const int acol = (tid & 1) * 4;
    const int bkr  = tid >> 5;
    const int bcl  = (tid & 31) * 4;

    const float* Ap = A + (size_t)(brow + arow) * K + acol;
    const float* Bp = Wg2 + (size_t)bkr * N + bcol + bcl;

    float4 ar = *(const float4*)Ap;
    float4 br = *(const float4*)Bp;
    As[0][acol + 0][arow] = ar.x;
    As[0][acol + 1][arow] = ar.y;
    As[0][acol + 2][arow] = ar.z;
    As[0][acol + 3][arow] = ar.w;
    *(float4*)&Bs[0][bkr][bcl] = br;
    __syncthreads();

    float acc[8][8];
#pragma unroll
    for (int i = 0; i < 8; i++)
#pragma unroll
        for (int j = 0; j < 8; j++) acc[i][j] = 0.0f;

    int buf = 0;
    for (int k0 = 8; k0 <= K; k0 += 8) {
        if (k0 < K) {
            ar = *(const float4*)(Ap + k0);
            br = *(const float4*)(Bp + (size_t)k0 * N);
        }
#pragma unroll
        for (int kk = 0; kk < 8; kk++) {
            float af[8], bf[8];
            *(float4*)&af[0] = *(float4*)&As[buf][kk][ty * 8];
            *(float4*)&af[4] = *(float4*)&As[buf][kk][ty * 8 + 4];
            *(float4*)&bf[0] = *(float4*)&Bs[buf][kk][tx * 8];
            *(float4*)&bf[4] = *(float4*)&Bs[buf][kk][tx * 8 + 4];
#pragma unroll
            for (int i = 0; i < 8; i++)
#pragma unroll
                for (int j = 0; j < 8; j++)
                    acc[i][j] = fmaf(af[i], bf[j], acc[i][j]);
        }
        if (k0 < K) {
            buf ^= 1;
            As[buf][acol + 0][arow] = ar.x;
            As[buf][acol + 1][arow] = ar.y;
            As[buf][acol + 2][arow] = ar.z;
            As[buf][acol + 3][arow] = ar.w;
            *(float4*)&Bs[buf][bkr][bcl] = br;
            __syncthreads();
        }
    }

#pragma unroll
    for (int i = 0; i < 8; i++) {
        float* Cp = g_gd + (size_t)(brow + ty * 8 + i) * N + bcol + tx * 8;
#pragma unroll
        for (int j0 = 0; j0 < 8; j0 += 4) {
            float4 o;
            o.x = acc[i][j0 + 0];
            o.y = acc[i][j0 + 1];
            o.z = acc[i][j0 + 2];
            o.w = acc[i][j0 + 3];
            *(float4*)(Cp + j0) = o;
        }
    }
}

// ============================================================
// Intra-chunk attention + per-chunk kv contribution A_c (fp32)
// decay[] lookup table replaces per-element expf (identical values).
// ============================================================
#define SM_QT   0
#define SM_KT   (64*132)
#define SM_VS   (2*64*132)
#define SM_SS   (2*64*132 + 128*68)
#define SM_LAM  (2*64*132 + 128*68 + 128*129)
#define SM_DEC  (SM_LAM + 128)
#define SMEM_INTRA_FLOATS (SM_DEC + 128)

__global__ __launch_bounds__(256) void attn_intra(
    const float* __restrict__ q, const float* __restrict__ k,
    const float* __restrict__ v)
{
    extern __shared__ float sm[];
    float* qT  = sm + SM_QT;
    float* kT  = sm + SM_KT;
    float* vs  = sm + SM_VS;
    float* Ss  = sm + SM_SS;
    float* lamk = sm + SM_LAM;
    float* decay = sm + SM_DEC;

    const int c = blockIdx.x, h = blockIdx.y, b = blockIdx.z;
    const int tid = threadIdx.x;
    const float s = head_slope(h);
    const size_t base = ((size_t)b * Nn + (size_t)c * Cc) * Ee + (size_t)h * Dd;

#pragma unroll
    for (int t = 0; t < 8; t++) {
        int e = tid + t * 256;
        int row = e >> 4;
        int d4 = (e & 15) * 4;
        const size_t g = base + (size_t)row * Ee + d4;
        float4 qv = *(const float4*)(q + g);
        qT[(d4 + 0) * 132 + row] = qv.x;
        qT[(d4 + 1) * 132 + row] = qv.y;
        qT[(d4 + 2) * 132 + row] = qv.z;
        qT[(d4 + 3) * 132 + row] = qv.w;
        float4 kv4 = *(const float4*)(k + g);
        kT[(d4 + 0) * 132 + row] = kv4.x;
        kT[(d4 + 1) * 132 + row] = kv4.y;
        kT[(d4 + 2) * 132 + row] = kv4.z;
        kT[(d4 + 3) * 132 + row] = kv4.w;
        *(float4*)&vs[row * 68 + d4] = *(const float4*)(v + g);
    }
    if (tid < 128) {
        lamk[tid] = expf(-s * (float)(Cc - 1 - tid));
        decay[tid] = expf(-s * (float)tid);
    }
    __syncthreads();

    const int tx = tid & 15, ty = tid >> 4;

    float acc[8][8];
#pragma unroll
    for (int i = 0; i < 8; i++)
#pragma unroll
        for (int j = 0; j < 8; j++) acc[i][j] = 0.0f;

    for (int d = 0; d < 64; d++) {
        float af[8], bf[8];
        *(float4*)&af[0] = *(float4*)&qT[d * 132 + ty * 8];
        *(float4*)&af[4] = *(float4*)&qT[d * 132 + ty * 8 + 4];
        *(float4*)&bf[0] = *(float4*)&kT[d * 132 + tx * 8];
        *(float4*)&bf[4] = *(float4*)&kT[d * 132 + tx * 8 + 4];
#pragma unroll
        for (int i = 0; i < 8; i++)
#pragma unroll
            for (int j = 0; j < 8; j++)
                acc[i][j] = fmaf(af[i], bf[j], acc[i][j]);
    }
#pragma unroll
    for (int ii = 0; ii < 8; ii++) {
        int i = ty * 8 + ii;
#pragma unroll
        for (int jj = 0; jj < 8; jj++) {
            int j = tx * 8 + jj;
            float val = 0.0f;
            if (i >= j) val = acc[ii][jj] * decay[i - j];
            Ss[i * 129 + j] = val;
        }
    }
    __syncthreads();

    float oc[8][4];
#pragma unroll
    for (int i = 0; i < 8; i++)
#pragma unroll
        for (int j = 0; j < 4; j++) oc[i][j] = 0.0f;

    for (int j = 0; j < 128; j++) {
        float bv[4];
        *(float4*)bv = *(float4*)&vs[j * 68 + tx * 4];
#pragma unroll
        for (int ii = 0; ii < 8; ii++) {
            float a = Ss[(ty * 8 + ii) * 129 + j];
#pragma unroll
            for (int dd = 0; dd < 4; dd++)
                oc[ii][dd] = fmaf(a, bv[dd], oc[ii][dd]);
        }
    }
#pragma unroll
    for (int ii = 0; ii < 8; ii++) {
        float4 o;
        o.x = oc[ii][0]; o.y = oc[ii][1]; o.z = oc[ii][2]; o.w = oc[ii][3];
        *(float4*)(g_o + base + (size_t)(ty * 8 + ii) * Ee + tx * 4) = o;
    }

    float ac[4][4];
#pragma unroll
    for (int i = 0; i < 4; i++)
#pragma unroll
        for (int j = 0; j < 4; j++) ac[i][j] = 0.0f;

    const int dr = ty * 4;
    for (int j = 0; j < 128; j++) {
        float lam = lamk[j];
        float bv[4];
        *(float4*)bv = *(float4*)&vs[j * 68 + tx * 4];
#pragma unroll
        for (int i = 0; i < 4; i++) {
            float a = kT[(dr + i) * 132 + j] * lam;
#pragma unroll
            for (int e2 = 0; e2 < 4; e2++)
                ac[i][e2] = fmaf(a, bv[e2], ac[i][e2]);
        }
    }
    float* Ab = g_A + ((((size_t)b * Hh + h) * NCk + c) * (Dd * Dd));
#pragma unroll
    for (int i = 0; i < 4; i++) {
        float4 o;
        o.x = ac[i][0]; o.y = ac[i][1]; o.z = ac[i][2]; o.w = ac[i][3];
        *(float4*)&Ab[(dr + i) * Dd + tx * 4] = o;
    }
}

// ============================================================
// kv prefix scan: one (b,h,element) chain per thread
// ============================================================
__global__ __launch_bounds__(256) void kv_scan()
{
    const int gidx = blockIdx.x * 256 + threadIdx.x;
    const int bh = gidx >> 12;
    const int e  = gidx & 4095;
    const int h  = bh & 15;
    const float s = head_slope(h);
    const float lamc = expf(-s * (float)Cc);

    size_t off = (size_t)bh * NCk * (Dd * Dd) + e;
    float kv = 0.0f;
#pragma unroll 4
    for (int c = 0; c < NCk; c++) {
        g_kv[off] = kv;
        kv = fmaf(lamc, kv, g_A[off]);
        off += Dd * Dd;
    }
}

// ============================================================
// Inter-chunk: o += lam_q[i] * (q @ kv_prefix)   [skips chunk 0]
// ============================================================
#define SMEM_INTER_FLOATS (128*68 + 64*68)

__global__ __launch_bounds__(256) void attn_inter(const float* __restrict__ q)
{
    extern __shared__ float smf[];
    float* qs  = smf;
    float* kvs = smf + 128 * 68;

    const int c = blockIdx.x + 1;       // chunk 0 has zero kv prefix
    const int h = blockIdx.y, b = blockIdx.z;
    const int tid = threadIdx.x;
    const float s = head_slope(h);
    const size_t base = ((size_t)b * Nn + (size_t)c * Cc) * Ee + (size_t)h * Dd;

#pragma unroll
    for (int t = 0; t < 8; t++) {
        int e = tid + t * 256;
        int row = e >> 4;
        int d4 = (e & 15) * 4;
        *(float4*)&qs[row * 68 + d4] = *(const float4*)(q + base + (size_t)row * Ee + d4);
    }
    const float* kvp = g_kv + (((size_t)b * Hh + h) * NCk + c) * (Dd * Dd);
#pragma unroll
    for (int t = 0; t < 4; t++) {
        int e = tid + t * 256;
        int row = e >> 4;
        int d4 = (e & 15) * 4;
        *(float4*)&kvs[row * 68 + d4] = *(const float4*)(kvp + row * Dd + d4);
    }
    __syncthreads();

    const int tx = tid & 15, ty = tid >> 4;
    float oc[8][4];
#pragma unroll
    for (int i = 0; i < 8; i++)
#pragma unroll
        for (int j = 0; j < 4; j++) oc[i][j] = 0.0f;

    for (int e2 = 0; e2 < 64; e2++) {
        float bv[4];
        *(float4*)bv = *(float4*)&kvs[e2 * 68 + tx * 4];
#pragma unroll
        for (int ii = 0; ii < 8; ii++) {
            float a = qs[(ty * 8 + ii) * 68 + e2];
#pragma unroll
            for (int dd = 0; dd < 4; dd++)
                oc[ii][dd] = fmaf(a, bv[dd], oc[ii][dd]);
        }
    }
#pragma unroll
    for (int ii = 0; ii < 8; ii++) {
        int i = ty * 8 + ii;
        float lamq = expf(-s * (float)(i + 1));
        float* op = g_o + base + (size_t)i * Ee + tx * 4;
        float4 prev = *(float4*)op;
        prev.x = fmaf(lamq, oc[ii][0], prev.x);
        prev.y = fmaf(lamq, oc[ii][1], prev.y);
        prev.z = fmaf(lamq, oc[ii][2], prev.z);
        prev.w = fmaf(lamq, oc[ii][3], prev.w);
        *(float4*)op = prev;
    }
}

// ============================================================
// LayerNorm + sigmoid(gd) * -> g_uh (half, K-PERMUTED)
// Warp-per-row reductions: no block barriers after initial load.
// ============================================================
__global__ __launch_bounds__(256) void ln_gate(
    const float* __restrict__ gamma, const float* __restrict__ beta)
{
    __shared__ float os[8 * 1024];

    const int tid = threadIdx.x;
    const size_t row0 = (size_t)blockIdx.x * 8;

#pragma unroll
    for (int t = 0; t < 8; t++) {
        int e = tid + t * 256;
        int r = e >> 8;
        int c4 = (e & 255) * 4;
        *(float4*)&os[r * 1024 + c4] = *(const float4*)(g_o + (row0 + r) * 1024 + c4);
    }
    __syncthreads();

    const int lane = tid & 31, wid = tid >> 5;
    const int r = wid;

    float sum = 0.0f;
#pragma unroll
    for (int i = 0; i < 32; i++) sum += os[r * 1024 + lane + i * 32];
#pragma unroll
    for (int o = 16; o; o >>= 1) sum += __shfl_xor_sync(0xffffffffu, sum, o);
    const float mu = sum * (1.0f / 1024.0f);

    float sq = 0.0f;
#pragma unroll
    for (int i = 0; i < 32; i++) {
        float d = os[r * 1024 + lane + i * 32] - mu;
        sq = fmaf(d, d, sq);
    }
#pragma unroll
    for (int o = 16; o; o >>= 1) sq += __shfl_xor_sync(0xffffffffu, sq, o);
    const float rs = rsqrtf(sq * (1.0f / 1024.0f) + 1e-5f);

    const int cbase = lane * 4;
#pragma unroll
    for (int t = 0; t < 8; t++) {
        int col = cbase + t * 128;
        float4 ov = *(float4*)&os[r * 1024 + col];
        float4 gd = *(const float4*)(g_gd + (row0 + r) * 1024 + col);
        float4 gm = *(const float4*)(gamma + col);
        float4 bt = *(const float4*)(beta + col);
        float ux = (fmaf((ov.x - mu) * rs, gm.x, bt.x)) * (1.0f / (1.0f + expf(-gd.x)));
        float uy = (fmaf((ov.y - mu) * rs, gm.y, bt.y)) * (1.0f / (1.0f + expf(-gd.y)));
        float uz = (fmaf((ov.z - mu) * rs, gm.z, bt.z)) * (1.0f / (1.0f + expf(-gd.z)));
        float uw = (fmaf((ov.w - mu) * rs, gm.w, bt.w)) * (1.0f / (1.0f + expf(-gd.w)));
        int o0 = col >> 1;
        size_t rb = (row0 + r) * 512;
        g_uh[rb + knew(o0)]     = packh2(ux, uy);
        g_uh[rb + knew(o0 + 1)] = packh2(uz, uw);
    }
}

// ============================================================
// host launch (sequential, single stream — R15 schedule)
// ============================================================
extern "C" void kernel_launch(void* const* d_in, const int* in_sizes, int n_in,
                              void* d_out, int out_size)
{
    const float* x     = (const float*)d_in[0];
    const float* Wq    = (const float*)d_in[1];
    const float* Wk    = (const float*)d_in[2];
    const float* Wv    = (const float*)d_in[3];
    const float* Wo    = (const float*)d_in[4];
    const float* gamma = (const float*)d_in[5];
    const float* beta  = (const float*)d_in[6];
    const float* Wg1   = (const float*)d_in[7];
    const float* Wg2   = (const float*)d_in[8];
    float* out = (float*)d_out;

    static bool init_done = false;
    static float *qp, *kp, *vp;
    if (!init_done) {
        cudaGetSymbolAddress((void**)&qp, g_q);
        cudaGetSymbolAddress((void**)&kp, g_k);
        cudaGetSymbolAddress((void**)&vp, g_v);
        cudaFuncSetAttribute(attn_intra, cudaFuncAttributeMaxDynamicSharedMemorySize,
                             SMEM_INTRA_FLOATS * (int)sizeof(float));
        cudaFuncSetAttribute(attn_inter, cudaFuncAttributeMaxDynamicSharedMemorySize,
                             SMEM_INTER_FLOATS * (int)sizeof(float));
        cudaFuncSetAttribute(gemm_qkv_f16, cudaFuncAttributeMaxDynamicSharedMemorySize,
                             GEMM_SMEM_BIG);
        cudaFuncSetAttribute(gemm_out_f16, cudaFuncAttributeMaxDynamicSharedMemorySize,
                             GEMM_SMEM_BIG);
        cudaFuncSetAttribute(gemm_g1_f16, cudaFuncAttributeMaxDynamicSharedMemorySize,
                             GEMM_SMEM_G1);
        init_done = true;
    }

    const int smem_intra = SMEM_INTRA_FLOATS * (int)sizeof(float);
    const int smem_inter = SMEM_INTER_FLOATS * (int)sizeof(float);

    dim3 blk(256);
    dim3 blk128(128);

    conv_x<<<4096, blk>>>(x);
    conv_wt<<<dim3(32, 32, 4), blk>>>(Wq, Wk, Wv, Wo);
    conv_wg1<<<dim3(2, 32), blk>>>(Wg1);

    gemm_qkv_f16<<<dim3(Ee / 128, Mm / 128, 3), blk128, GEMM_SMEM_BIG>>>();
    gemm_g1_f16<<<Mm / 128, blk128, GEMM_SMEM_G1>>>();
    sgemm_gd<<<dim3(Ee / 128, Mm / 128), blk>>>(Wg2);

    attn_intra<<<dim3(NCk, Hh, Bb), blk, smem_intra>>>(qp, kp, vp);
    kv_scan<<<512, blk>>>();
    attn_inter<<<dim3(NCk - 1, Hh, Bb), blk, smem_inter>>>(qp);

    ln_gate<<<Mm / 8, blk>>>(gamma, beta);

    gemm_out_f16<<<dim3(Ee / 128, Mm / 128), blk128, GEMM_SMEM_BIG>>>(out);
}